// round 1
// baseline (speedup 1.0000x reference)
#include <cuda_runtime.h>
#include <math.h>

// Problem constants
#define T_TOK 4096
#define H_DIM 1024
#define I_DIM 2048
#define N_EXP 8

// ---------------- scratch (static device globals; no allocs) ----------------
__device__ float g_xs[(size_t)T_TOK * H_DIM];          // shared-expert LN(x)   16MB
__device__ int   g_cnt[N_EXP];                          // tokens per expert
__device__ int   g_tok[N_EXP][T_TOK];                   // token index per bucket row
__device__ float g_wt [N_EXP][T_TOK];                   // combine weight
__device__ int   g_slot[N_EXP][T_TOK];                  // output slot = 2*t + rank
__device__ float g_hidden[(size_t)2 * T_TOK * I_DIM];   // routed SwiGLU hidden  64MB
__device__ float g_eout [(size_t)2 * T_TOK * H_DIM];    // routed expert out     32MB
__device__ float g_shid [(size_t)T_TOK * I_DIM];        // shared hidden         32MB
__device__ float g_shout[(size_t)T_TOK * H_DIM];        // shared out            16MB
__device__ float g_zsq[T_TOK];                          // z^2 per token

// ---------------- zero counters ----------------
__global__ void zero_cnt_kernel() {
    if (threadIdx.x < N_EXP) g_cnt[threadIdx.x] = 0;
}

// ---------------- router: LN + logits + softmax/top2 + shared LN + bucket ----
__global__ void __launch_bounds__(256) router_kernel(
    const float* __restrict__ x,
    const float* __restrict__ ln_g, const float* __restrict__ ln_b,
    const float* __restrict__ gate_w, const float* __restrict__ bias,
    const float* __restrict__ sh_g, const float* __restrict__ sh_b)
{
    __shared__ float sx[H_DIM];
    __shared__ float sred[8], sred2[8];
    __shared__ float s_mean, s_rstd;
    __shared__ float logits[N_EXP];

    const int t   = blockIdx.x;
    const int tid = threadIdx.x;
    const float* xr = x + (size_t)t * H_DIM;

    float s = 0.f, s2 = 0.f;
#pragma unroll
    for (int i = 0; i < H_DIM / 256; i++) {
        float v = xr[tid + i * 256];
        sx[tid + i * 256] = v;
        s += v; s2 += v * v;
    }
#pragma unroll
    for (int o = 16; o; o >>= 1) {
        s  += __shfl_xor_sync(0xffffffffu, s,  o);
        s2 += __shfl_xor_sync(0xffffffffu, s2, o);
    }
    const int wid = tid >> 5, lane = tid & 31;
    if (lane == 0) { sred[wid] = s; sred2[wid] = s2; }
    __syncthreads();
    if (tid == 0) {
        float a = 0.f, b = 0.f;
        for (int i = 0; i < 8; i++) { a += sred[i]; b += sred2[i]; }
        float mean = a * (1.f / H_DIM);
        float var  = b * (1.f / H_DIM) - mean * mean;
        s_mean = mean;
        s_rstd = rsqrtf(var + 1e-5f);
    }
    __syncthreads();
    const float mean = s_mean, rstd = s_rstd;

    // logits: warp e computes expert e
    {
        const float* gw = gate_w + wid * H_DIM;
        float acc = 0.f;
        for (int i = lane; i < H_DIM; i += 32) {
            float hn = (sx[i] - mean) * rstd * ln_g[i] + ln_b[i];
            acc += hn * gw[i];
        }
#pragma unroll
        for (int o = 16; o; o >>= 1) acc += __shfl_xor_sync(0xffffffffu, acc, o);
        if (lane == 0) logits[wid] = acc + bias[wid];
    }

    // shared-expert LN (same x, same stats)
#pragma unroll
    for (int i = 0; i < H_DIM / 256; i++) {
        int idx = tid + i * 256;
        g_xs[(size_t)t * H_DIM + idx] = (sx[idx] - mean) * rstd * sh_g[idx] + sh_b[idx];
    }
    __syncthreads();

    if (tid == 0) {
        float mx = logits[0];
#pragma unroll
        for (int e = 1; e < N_EXP; e++) mx = fmaxf(mx, logits[e]);
        float p[N_EXP]; float se = 0.f;
#pragma unroll
        for (int e = 0; e < N_EXP; e++) { p[e] = expf(logits[e] - mx); se += p[e]; }
        float z = mx + logf(se);
        g_zsq[t] = z * z;
        int e1 = 0;
#pragma unroll
        for (int e = 1; e < N_EXP; e++) if (p[e] > p[e1]) e1 = e;
        int e2 = (e1 == 0) ? 1 : 0;
#pragma unroll
        for (int e = 0; e < N_EXP; e++) if (e != e1 && p[e] > p[e2]) e2 = e;
        float inv = 1.f / se;
        float p1 = p[e1] * inv, p2 = p[e2] * inv;
        float sm = fmaxf(p1 + p2, 1e-5f);
        float w1 = p1 / sm, w2 = p2 / sm;
        int pos = atomicAdd(&g_cnt[e1], 1);
        g_tok[e1][pos] = t; g_wt[e1][pos] = w1; g_slot[e1][pos] = 2 * t;
        pos = atomicAdd(&g_cnt[e2], 1);
        g_tok[e2][pos] = t; g_wt[e2][pos] = w2; g_slot[e2][pos] = 2 * t + 1;
    }
}

// ---------------- fused gate/up GEMM + SwiGLU ----------------
// C_hidden[row] = silu(X @ Wg^T) * (X @ Wu^T), grouped per expert (routed) or dense (shared)
#define BM 64
#define BN 64
#define BK 16

__global__ void __launch_bounds__(256) gemm_gateup(
    const float* __restrict__ x_routed,       // hidden_states (only used when routed)
    const float* __restrict__ Wg_all,
    const float* __restrict__ Wu_all,
    int routed)
{
    const int e = blockIdx.z;
    const int cnt = routed ? g_cnt[e] : T_TOK;
    const int m0 = blockIdx.x * BM;
    if (m0 >= cnt) return;
    const int n0 = blockIdx.y * BN;

    const float* xsrc = routed ? x_routed : g_xs;
    float* hid        = routed ? g_hidden : g_shid;
    const float* Wg = Wg_all + (size_t)e * I_DIM * H_DIM;
    const float* Wu = Wu_all + (size_t)e * I_DIM * H_DIM;

    __shared__ float As[BK][BM];
    __shared__ float Bg[BK][BN];
    __shared__ float Bu[BK][BN];

    const int tid  = threadIdx.x;
    const int lrow = tid >> 2;          // 0..63
    const int lcol = (tid & 3) * 4;     // 0,4,8,12
    const int tx   = tid & 15;          // 0..15
    const int ty   = tid >> 4;          // 0..15

    const int am = m0 + lrow;
    const float* aptr = nullptr;
    if (am < cnt) {
        int arow = routed ? g_tok[e][am] : am;
        aptr = xsrc + (size_t)arow * H_DIM;
    }
    const float* bgptr = Wg + (size_t)(n0 + lrow) * H_DIM;
    const float* buptr = Wu + (size_t)(n0 + lrow) * H_DIM;

    float accg[4][4] = {}, accu[4][4] = {};

    for (int k0 = 0; k0 < H_DIM; k0 += BK) {
        float4 av = aptr ? *(const float4*)(aptr + k0 + lcol) : make_float4(0.f, 0.f, 0.f, 0.f);
        float4 gv = *(const float4*)(bgptr + k0 + lcol);
        float4 uv = *(const float4*)(buptr + k0 + lcol);
        __syncthreads();
        As[lcol + 0][lrow] = av.x; As[lcol + 1][lrow] = av.y;
        As[lcol + 2][lrow] = av.z; As[lcol + 3][lrow] = av.w;
        Bg[lcol + 0][lrow] = gv.x; Bg[lcol + 1][lrow] = gv.y;
        Bg[lcol + 2][lrow] = gv.z; Bg[lcol + 3][lrow] = gv.w;
        Bu[lcol + 0][lrow] = uv.x; Bu[lcol + 1][lrow] = uv.y;
        Bu[lcol + 2][lrow] = uv.z; Bu[lcol + 3][lrow] = uv.w;
        __syncthreads();
#pragma unroll
        for (int kk = 0; kk < BK; kk++) {
            float a[4], bg4[4], bu4[4];
#pragma unroll
            for (int i = 0; i < 4; i++) a[i] = As[kk][ty * 4 + i];
#pragma unroll
            for (int j = 0; j < 4; j++) { bg4[j] = Bg[kk][tx * 4 + j]; bu4[j] = Bu[kk][tx * 4 + j]; }
#pragma unroll
            for (int i = 0; i < 4; i++)
#pragma unroll
                for (int j = 0; j < 4; j++) {
                    accg[i][j] += a[i] * bg4[j];
                    accu[i][j] += a[i] * bu4[j];
                }
        }
    }

#pragma unroll
    for (int i = 0; i < 4; i++) {
        int m = m0 + ty * 4 + i;
        if (m >= cnt) continue;
        int orow = routed ? g_slot[e][m] : m;
        float* op = hid + (size_t)orow * I_DIM + n0 + tx * 4;
#pragma unroll
        for (int j = 0; j < 4; j++) {
            float g = accg[i][j];
            float u = accu[i][j];
            float sg = g / (1.f + expf(-g));   // silu
            op[j] = sg * u;
        }
    }
}

// ---------------- down GEMM (+ combine weight for routed) ----------------
__global__ void __launch_bounds__(256) gemm_down(
    const float* __restrict__ Wd_all,
    int routed)
{
    const int e = blockIdx.z;
    const int cnt = routed ? g_cnt[e] : T_TOK;
    const int m0 = blockIdx.x * BM;
    if (m0 >= cnt) return;
    const int n0 = blockIdx.y * BN;

    const float* hid = routed ? g_hidden : g_shid;
    const float* Wd  = Wd_all + (size_t)e * H_DIM * I_DIM;

    __shared__ float As[BK][BM];
    __shared__ float Bs[BK][BN];

    const int tid  = threadIdx.x;
    const int lrow = tid >> 2;
    const int lcol = (tid & 3) * 4;
    const int tx   = tid & 15;
    const int ty   = tid >> 4;

    const int am = m0 + lrow;
    const float* aptr = nullptr;
    if (am < cnt) {
        int arow = routed ? g_slot[e][am] : am;
        aptr = hid + (size_t)arow * I_DIM;
    }
    const float* bptr = Wd + (size_t)(n0 + lrow) * I_DIM;

    float acc[4][4] = {};

    for (int k0 = 0; k0 < I_DIM; k0 += BK) {
        float4 av = aptr ? *(const float4*)(aptr + k0 + lcol) : make_float4(0.f, 0.f, 0.f, 0.f);
        float4 bv = *(const float4*)(bptr + k0 + lcol);
        __syncthreads();
        As[lcol + 0][lrow] = av.x; As[lcol + 1][lrow] = av.y;
        As[lcol + 2][lrow] = av.z; As[lcol + 3][lrow] = av.w;
        Bs[lcol + 0][lrow] = bv.x; Bs[lcol + 1][lrow] = bv.y;
        Bs[lcol + 2][lrow] = bv.z; Bs[lcol + 3][lrow] = bv.w;
        __syncthreads();
#pragma unroll
        for (int kk = 0; kk < BK; kk++) {
            float a[4], b4[4];
#pragma unroll
            for (int i = 0; i < 4; i++) a[i] = As[kk][ty * 4 + i];
#pragma unroll
            for (int j = 0; j < 4; j++) b4[j] = Bs[kk][tx * 4 + j];
#pragma unroll
            for (int i = 0; i < 4; i++)
#pragma unroll
                for (int j = 0; j < 4; j++) acc[i][j] += a[i] * b4[j];
        }
    }

#pragma unroll
    for (int i = 0; i < 4; i++) {
        int m = m0 + ty * 4 + i;
        if (m >= cnt) continue;
        if (routed) {
            int orow = g_slot[e][m];
            float w  = g_wt[e][m];
            float* op = g_eout + (size_t)orow * H_DIM + n0 + tx * 4;
#pragma unroll
            for (int j = 0; j < 4; j++) op[j] = acc[i][j] * w;
        } else {
            float* op = g_shout + (size_t)m * H_DIM + n0 + tx * 4;
#pragma unroll
            for (int j = 0; j < 4; j++) op[j] = acc[i][j];
        }
    }
}

// ---------------- combine: routed(2 slots) + shared*sigmoid(gate) ----------------
__global__ void __launch_bounds__(256) combine_kernel(
    float* __restrict__ out, const float* __restrict__ shared_gate)
{
    const int idx = blockIdx.x * 256 + threadIdx.x;     // [0, T*H)
    const float sig = 1.f / (1.f + expf(-shared_gate[0]));
    const int t = idx >> 10;           // /H_DIM
    const int h = idx & (H_DIM - 1);
    out[idx] = g_eout[(size_t)(2 * t) * H_DIM + h]
             + g_eout[(size_t)(2 * t + 1) * H_DIM + h]
             + g_shout[idx] * sig;
}

// ---------------- aux z-loss (deterministic tree reduction) ----------------
__global__ void __launch_bounds__(256) aux_kernel(float* __restrict__ out)
{
    __shared__ float red[256];
    const int tid = threadIdx.x;
    float s = 0.f;
    for (int i = tid; i < T_TOK; i += 256) s += g_zsq[i];
    red[tid] = s;
    __syncthreads();
    for (int o = 128; o; o >>= 1) {
        if (tid < o) red[tid] += red[tid + o];
        __syncthreads();
    }
    if (tid == 0) out[(size_t)T_TOK * H_DIM] = red[0] * (1e-4f / T_TOK);
}

// ---------------- launch ----------------
extern "C" void kernel_launch(void* const* d_in, const int* in_sizes, int n_in,
                              void* d_out, int out_size)
{
    const float* x      = (const float*)d_in[0];
    const float* ln_g   = (const float*)d_in[1];
    const float* ln_b   = (const float*)d_in[2];
    const float* gate_w = (const float*)d_in[3];
    const float* bias   = (const float*)d_in[4];
    const float* Wg     = (const float*)d_in[5];
    const float* Wu     = (const float*)d_in[6];
    const float* Wd     = (const float*)d_in[7];
    const float* sh_g   = (const float*)d_in[8];
    const float* sh_b   = (const float*)d_in[9];
    const float* sWg    = (const float*)d_in[10];
    const float* sWu    = (const float*)d_in[11];
    const float* sWd    = (const float*)d_in[12];
    const float* sgate  = (const float*)d_in[13];
    float* out = (float*)d_out;

    zero_cnt_kernel<<<1, 32>>>();
    router_kernel<<<T_TOK, 256>>>(x, ln_g, ln_b, gate_w, bias, sh_g, sh_b);

    // routed gate/up (grid covers worst-case n_e = T; blocks early-exit)
    dim3 gu_grid(T_TOK / BM, I_DIM / BN, N_EXP);
    gemm_gateup<<<gu_grid, 256>>>(x, Wg, Wu, 1);
    // shared gate/up
    dim3 gus_grid(T_TOK / BM, I_DIM / BN, 1);
    gemm_gateup<<<gus_grid, 256>>>(nullptr, sWg, sWu, 0);

    // routed down (+weight)
    dim3 dn_grid(T_TOK / BM, H_DIM / BN, N_EXP);
    gemm_down<<<dn_grid, 256>>>(Wd, 1);
    // shared down
    dim3 dns_grid(T_TOK / BM, H_DIM / BN, 1);
    gemm_down<<<dns_grid, 256>>>(sWd, 0);

    combine_kernel<<<(T_TOK * H_DIM) / 256, 256>>>(out, sgate);
    aux_kernel<<<1, 256>>>(out);
}

// round 3
// speedup vs baseline: 2.1793x; 2.1793x over previous
#include <cuda_runtime.h>
#include <cuda_fp16.h>
#include <stdint.h>
#include <math.h>

// Problem constants
#define T_TOK 4096
#define H_DIM 1024
#define I_DIM 2048
#define N_EXP 8

// ---------------- scratch (static device globals; no allocs) ----------------
__device__ float g_xs[(size_t)T_TOK * H_DIM];          // shared-expert LN(x)
__device__ int   g_cnt[N_EXP];
__device__ int   g_tok[N_EXP][T_TOK];
__device__ float g_wt [N_EXP][T_TOK];
__device__ int   g_slot[N_EXP][T_TOK];                  // output slot = 2*t + rank
__device__ float g_hidden[(size_t)2 * T_TOK * I_DIM];   // routed SwiGLU hidden
__device__ float g_eout [(size_t)2 * T_TOK * H_DIM];    // routed expert out
__device__ float g_shid [(size_t)T_TOK * I_DIM];        // shared hidden
__device__ float g_shout[(size_t)T_TOK * H_DIM];        // shared out
__device__ float g_zsq[T_TOK];

// ---------------- zero counters ----------------
__global__ void zero_cnt_kernel() {
    if (threadIdx.x < N_EXP) g_cnt[threadIdx.x] = 0;
}

// ---------------- router ----------------
__global__ void __launch_bounds__(256) router_kernel(
    const float* __restrict__ x,
    const float* __restrict__ ln_g, const float* __restrict__ ln_b,
    const float* __restrict__ gate_w, const float* __restrict__ bias,
    const float* __restrict__ sh_g, const float* __restrict__ sh_b)
{
    __shared__ float sx[H_DIM];
    __shared__ float sred[8], sred2[8];
    __shared__ float s_mean, s_rstd;
    __shared__ float logits[N_EXP];

    const int t   = blockIdx.x;
    const int tid = threadIdx.x;
    const float* xr = x + (size_t)t * H_DIM;

    float s = 0.f, s2 = 0.f;
#pragma unroll
    for (int i = 0; i < H_DIM / 256; i++) {
        float v = xr[tid + i * 256];
        sx[tid + i * 256] = v;
        s += v; s2 += v * v;
    }
#pragma unroll
    for (int o = 16; o; o >>= 1) {
        s  += __shfl_xor_sync(0xffffffffu, s,  o);
        s2 += __shfl_xor_sync(0xffffffffu, s2, o);
    }
    const int wid = tid >> 5, lane = tid & 31;
    if (lane == 0) { sred[wid] = s; sred2[wid] = s2; }
    __syncthreads();
    if (tid == 0) {
        float a = 0.f, b = 0.f;
        for (int i = 0; i < 8; i++) { a += sred[i]; b += sred2[i]; }
        float mean = a * (1.f / H_DIM);
        float var  = b * (1.f / H_DIM) - mean * mean;
        s_mean = mean;
        s_rstd = rsqrtf(var + 1e-5f);
    }
    __syncthreads();
    const float mean = s_mean, rstd = s_rstd;

    {
        const float* gw = gate_w + wid * H_DIM;
        float acc = 0.f;
        for (int i = lane; i < H_DIM; i += 32) {
            float hn = (sx[i] - mean) * rstd * ln_g[i] + ln_b[i];
            acc += hn * gw[i];
        }
#pragma unroll
        for (int o = 16; o; o >>= 1) acc += __shfl_xor_sync(0xffffffffu, acc, o);
        if (lane == 0) logits[wid] = acc + bias[wid];
    }

#pragma unroll
    for (int i = 0; i < H_DIM / 256; i++) {
        int idx = tid + i * 256;
        g_xs[(size_t)t * H_DIM + idx] = (sx[idx] - mean) * rstd * sh_g[idx] + sh_b[idx];
    }
    __syncthreads();

    if (tid == 0) {
        float mx = logits[0];
#pragma unroll
        for (int e = 1; e < N_EXP; e++) mx = fmaxf(mx, logits[e]);
        float p[N_EXP]; float se = 0.f;
#pragma unroll
        for (int e = 0; e < N_EXP; e++) { p[e] = expf(logits[e] - mx); se += p[e]; }
        float z = mx + logf(se);
        g_zsq[t] = z * z;
        int e1 = 0;
#pragma unroll
        for (int e = 1; e < N_EXP; e++) if (p[e] > p[e1]) e1 = e;
        int e2 = (e1 == 0) ? 1 : 0;
#pragma unroll
        for (int e = 0; e < N_EXP; e++) if (e != e1 && p[e] > p[e2]) e2 = e;
        float inv = 1.f / se;
        float p1 = p[e1] * inv, p2 = p[e2] * inv;
        float sm = fmaxf(p1 + p2, 1e-5f);
        int pos = atomicAdd(&g_cnt[e1], 1);
        g_tok[e1][pos] = t; g_wt[e1][pos] = p1 / sm; g_slot[e1][pos] = 2 * t;
        pos = atomicAdd(&g_cnt[e2], 1);
        g_tok[e2][pos] = t; g_wt[e2][pos] = p2 / sm; g_slot[e2][pos] = 2 * t + 1;
    }
}

// ---------------- tensor-core GEMMs ----------------
#define BM 128
#define BN 64
#define BK 32
#define PADM 136     // half2 units per k2-row of A smem
#define PADN 72      // half2 units per k2-row of B smem

#define MMA16816(d, a, b) \
  asm volatile("mma.sync.aligned.m16n8k16.row.col.f32.f16.f16.f32 " \
    "{%0,%1,%2,%3}, {%4,%5,%6,%7}, {%8,%9}, {%0,%1,%2,%3};" \
    : "+f"((d)[0]), "+f"((d)[1]), "+f"((d)[2]), "+f"((d)[3]) \
    : "r"((a)[0]), "r"((a)[1]), "r"((a)[2]), "r"((a)[3]), "r"((b)[0]), "r"((b)[1]))

__device__ __forceinline__ uint32_t h2u(half2 h) { return *(uint32_t*)&h; }

// fused gate/up GEMM + SwiGLU
__global__ void __launch_bounds__(256) gemm_gateup(
    const float* __restrict__ x_routed,
    const float* __restrict__ Wg_all,
    const float* __restrict__ Wu_all,
    int routed)
{
    const int e = blockIdx.z;
    const int cnt = routed ? g_cnt[e] : T_TOK;
    const int m0 = blockIdx.x * BM;
    if (m0 >= cnt) return;
    const int n0 = blockIdx.y * BN;

    const float* xsrc = routed ? x_routed : g_xs;
    float* hid        = routed ? g_hidden : g_shid;
    const float* Wg = Wg_all + (size_t)e * I_DIM * H_DIM;
    const float* Wu = Wu_all + (size_t)e * I_DIM * H_DIM;

    __shared__ half2 As[2][BK/2][PADM];
    __shared__ half2 Bgs[2][BK/2][PADN];
    __shared__ half2 Bus[2][BK/2][PADN];

    const int tid  = threadIdx.x;
    const int lane = tid & 31;
    const int wid  = tid >> 5;
    const int wm   = (wid & 3) * 32;
    const int wn   = (wid >> 2) * 32;
    const int fr   = lane >> 2;   // 0..7
    const int fc   = lane & 3;    // 0..3

    // gmem->smem mappings
    const int am  = tid & 127;        // A row within tile
    const int af4 = tid >> 7;         // A float4 base {0,1}
    const float* aptr = nullptr;
    if (m0 + am < cnt) {
        int r = routed ? g_tok[e][m0 + am] : (m0 + am);
        aptr = xsrc + (size_t)r * H_DIM;
    }
    const int bn  = tid & 63;
    const int bf4 = tid >> 6;         // {0..3}
    const float* bgp = Wg + (size_t)(n0 + bn) * H_DIM;
    const float* bup = Wu + (size_t)(n0 + bn) * H_DIM;

    float acg[2][4][4] = {};
    float acu[2][4][4] = {};

    const int NC = H_DIM / BK;  // 32
    const float4 z4 = make_float4(0.f, 0.f, 0.f, 0.f);

    // ---- chunk 0 ----
    {
        float4 ra[4], rg[2], ru[2];
#pragma unroll
        for (int i = 0; i < 4; i++)
            ra[i] = aptr ? *(const float4*)(aptr + (af4 + 2*i) * 4) : z4;
#pragma unroll
        for (int i = 0; i < 2; i++) {
            rg[i] = *(const float4*)(bgp + (bf4 + 4*i) * 4);
            ru[i] = *(const float4*)(bup + (bf4 + 4*i) * 4);
        }
#pragma unroll
        for (int i = 0; i < 4; i++) {
            int f4 = af4 + 2*i;
            As[0][f4*2  ][am] = __floats2half2_rn(ra[i].x, ra[i].y);
            As[0][f4*2+1][am] = __floats2half2_rn(ra[i].z, ra[i].w);
        }
#pragma unroll
        for (int i = 0; i < 2; i++) {
            int f4 = bf4 + 4*i;
            Bgs[0][f4*2  ][bn] = __floats2half2_rn(rg[i].x, rg[i].y);
            Bgs[0][f4*2+1][bn] = __floats2half2_rn(rg[i].z, rg[i].w);
            Bus[0][f4*2  ][bn] = __floats2half2_rn(ru[i].x, ru[i].y);
            Bus[0][f4*2+1][bn] = __floats2half2_rn(ru[i].z, ru[i].w);
        }
    }
    __syncthreads();

    for (int c = 1; c <= NC; c++) {
        float4 ra[4], rg[2], ru[2];
        if (c < NC) {
            const int k0 = c * BK;
#pragma unroll
            for (int i = 0; i < 4; i++)
                ra[i] = aptr ? *(const float4*)(aptr + k0 + (af4 + 2*i) * 4) : z4;
#pragma unroll
            for (int i = 0; i < 2; i++) {
                rg[i] = *(const float4*)(bgp + k0 + (bf4 + 4*i) * 4);
                ru[i] = *(const float4*)(bup + k0 + (bf4 + 4*i) * 4);
            }
        }
        const int pb = (c + 1) & 1;   // buffer holding chunk c-1
#pragma unroll
        for (int s = 0; s < 2; s++) {
            const int k2 = s * 8;
            uint32_t a[2][4];
#pragma unroll
            for (int mt = 0; mt < 2; mt++) {
                int mb = wm + mt * 16;
                a[mt][0] = h2u(As[pb][k2 + fc    ][mb + fr    ]);
                a[mt][1] = h2u(As[pb][k2 + fc    ][mb + fr + 8]);
                a[mt][2] = h2u(As[pb][k2 + fc + 4][mb + fr    ]);
                a[mt][3] = h2u(As[pb][k2 + fc + 4][mb + fr + 8]);
            }
            uint32_t bg[4][2], bu[4][2];
#pragma unroll
            for (int nt = 0; nt < 4; nt++) {
                int nb = wn + nt * 8 + fr;
                bg[nt][0] = h2u(Bgs[pb][k2 + fc    ][nb]);
                bg[nt][1] = h2u(Bgs[pb][k2 + fc + 4][nb]);
                bu[nt][0] = h2u(Bus[pb][k2 + fc    ][nb]);
                bu[nt][1] = h2u(Bus[pb][k2 + fc + 4][nb]);
            }
#pragma unroll
            for (int mt = 0; mt < 2; mt++)
#pragma unroll
                for (int nt = 0; nt < 4; nt++) {
                    MMA16816(acg[mt][nt], a[mt], bg[nt]);
                    MMA16816(acu[mt][nt], a[mt], bu[nt]);
                }
        }
        if (c < NC) {
            __syncthreads();
            const int cb = c & 1;
#pragma unroll
            for (int i = 0; i < 4; i++) {
                int f4 = af4 + 2*i;
                As[cb][f4*2  ][am] = __floats2half2_rn(ra[i].x, ra[i].y);
                As[cb][f4*2+1][am] = __floats2half2_rn(ra[i].z, ra[i].w);
            }
#pragma unroll
            for (int i = 0; i < 2; i++) {
                int f4 = bf4 + 4*i;
                Bgs[cb][f4*2  ][bn] = __floats2half2_rn(rg[i].x, rg[i].y);
                Bgs[cb][f4*2+1][bn] = __floats2half2_rn(rg[i].z, rg[i].w);
                Bus[cb][f4*2  ][bn] = __floats2half2_rn(ru[i].x, ru[i].y);
                Bus[cb][f4*2+1][bn] = __floats2half2_rn(ru[i].z, ru[i].w);
            }
            __syncthreads();
        }
    }

    // epilogue: silu(g)*u
#pragma unroll
    for (int mt = 0; mt < 2; mt++) {
#pragma unroll
        for (int i2 = 0; i2 < 2; i2++) {
            int row = wm + mt * 16 + fr + i2 * 8;
            int m = m0 + row;
            if (m >= cnt) continue;
            int orow = routed ? g_slot[e][m] : m;
            float* op = hid + (size_t)orow * I_DIM + n0;
#pragma unroll
            for (int nt = 0; nt < 4; nt++) {
                int col = wn + nt * 8 + 2 * fc;
                float g0 = acg[mt][nt][i2*2+0], g1 = acg[mt][nt][i2*2+1];
                float u0 = acu[mt][nt][i2*2+0], u1 = acu[mt][nt][i2*2+1];
                float2 v;
                v.x = (g0 / (1.f + expf(-g0))) * u0;
                v.y = (g1 / (1.f + expf(-g1))) * u1;
                *(float2*)(op + col) = v;
            }
        }
    }
}

// down GEMM (+ combine weight for routed)
__global__ void __launch_bounds__(256) gemm_down(
    const float* __restrict__ Wd_all,
    int routed)
{
    const int e = blockIdx.z;
    const int cnt = routed ? g_cnt[e] : T_TOK;
    const int m0 = blockIdx.x * BM;
    if (m0 >= cnt) return;
    const int n0 = blockIdx.y * BN;

    const float* hid = routed ? g_hidden : g_shid;
    const float* Wd  = Wd_all + (size_t)e * H_DIM * I_DIM;

    __shared__ half2 As[2][BK/2][PADM];
    __shared__ half2 Bs[2][BK/2][PADN];

    const int tid  = threadIdx.x;
    const int lane = tid & 31;
    const int wid  = tid >> 5;
    const int wm   = (wid & 3) * 32;
    const int wn   = (wid >> 2) * 32;
    const int fr   = lane >> 2;
    const int fc   = lane & 3;

    const int am  = tid & 127;
    const int af4 = tid >> 7;
    const float* aptr = nullptr;
    if (m0 + am < cnt) {
        int aslot = routed ? g_slot[e][m0 + am] : (m0 + am);
        aptr = hid + (size_t)aslot * I_DIM;
    }
    const int bn  = tid & 63;
    const int bf4 = tid >> 6;
    const float* bp = Wd + (size_t)(n0 + bn) * I_DIM;

    float acc[2][4][4] = {};
    const int NC = I_DIM / BK;  // 64
    const float4 z4 = make_float4(0.f, 0.f, 0.f, 0.f);

    {
        float4 ra[4], rb[2];
#pragma unroll
        for (int i = 0; i < 4; i++)
            ra[i] = aptr ? *(const float4*)(aptr + (af4 + 2*i) * 4) : z4;
#pragma unroll
        for (int i = 0; i < 2; i++)
            rb[i] = *(const float4*)(bp + (bf4 + 4*i) * 4);
#pragma unroll
        for (int i = 0; i < 4; i++) {
            int f4 = af4 + 2*i;
            As[0][f4*2  ][am] = __floats2half2_rn(ra[i].x, ra[i].y);
            As[0][f4*2+1][am] = __floats2half2_rn(ra[i].z, ra[i].w);
        }
#pragma unroll
        for (int i = 0; i < 2; i++) {
            int f4 = bf4 + 4*i;
            Bs[0][f4*2  ][bn] = __floats2half2_rn(rb[i].x, rb[i].y);
            Bs[0][f4*2+1][bn] = __floats2half2_rn(rb[i].z, rb[i].w);
        }
    }
    __syncthreads();

    for (int c = 1; c <= NC; c++) {
        float4 ra[4], rb[2];
        if (c < NC) {
            const int k0 = c * BK;
#pragma unroll
            for (int i = 0; i < 4; i++)
                ra[i] = aptr ? *(const float4*)(aptr + k0 + (af4 + 2*i) * 4) : z4;
#pragma unroll
            for (int i = 0; i < 2; i++)
                rb[i] = *(const float4*)(bp + k0 + (bf4 + 4*i) * 4);
        }
        const int pb = (c + 1) & 1;
#pragma unroll
        for (int s = 0; s < 2; s++) {
            const int k2 = s * 8;
            uint32_t a[2][4];
#pragma unroll
            for (int mt = 0; mt < 2; mt++) {
                int mb = wm + mt * 16;
                a[mt][0] = h2u(As[pb][k2 + fc    ][mb + fr    ]);
                a[mt][1] = h2u(As[pb][k2 + fc    ][mb + fr + 8]);
                a[mt][2] = h2u(As[pb][k2 + fc + 4][mb + fr    ]);
                a[mt][3] = h2u(As[pb][k2 + fc + 4][mb + fr + 8]);
            }
            uint32_t b[4][2];
#pragma unroll
            for (int nt = 0; nt < 4; nt++) {
                int nb = wn + nt * 8 + fr;
                b[nt][0] = h2u(Bs[pb][k2 + fc    ][nb]);
                b[nt][1] = h2u(Bs[pb][k2 + fc + 4][nb]);
            }
#pragma unroll
            for (int mt = 0; mt < 2; mt++)
#pragma unroll
                for (int nt = 0; nt < 4; nt++)
                    MMA16816(acc[mt][nt], a[mt], b[nt]);
        }
        if (c < NC) {
            __syncthreads();
            const int cb = c & 1;
#pragma unroll
            for (int i = 0; i < 4; i++) {
                int f4 = af4 + 2*i;
                As[cb][f4*2  ][am] = __floats2half2_rn(ra[i].x, ra[i].y);
                As[cb][f4*2+1][am] = __floats2half2_rn(ra[i].z, ra[i].w);
            }
#pragma unroll
            for (int i = 0; i < 2; i++) {
                int f4 = bf4 + 4*i;
                Bs[cb][f4*2  ][bn] = __floats2half2_rn(rb[i].x, rb[i].y);
                Bs[cb][f4*2+1][bn] = __floats2half2_rn(rb[i].z, rb[i].w);
            }
            __syncthreads();
        }
    }

#pragma unroll
    for (int mt = 0; mt < 2; mt++) {
#pragma unroll
        for (int i2 = 0; i2 < 2; i2++) {
            int row = wm + mt * 16 + fr + i2 * 8;
            int m = m0 + row;
            if (m >= cnt) continue;
            if (routed) {
                int orow = g_slot[e][m];
                float w  = g_wt[e][m];
                float* op = g_eout + (size_t)orow * H_DIM + n0;
#pragma unroll
                for (int nt = 0; nt < 4; nt++) {
                    int col = wn + nt * 8 + 2 * fc;
                    float2 v;
                    v.x = acc[mt][nt][i2*2+0] * w;
                    v.y = acc[mt][nt][i2*2+1] * w;
                    *(float2*)(op + col) = v;
                }
            } else {
                float* op = g_shout + (size_t)m * H_DIM + n0;
#pragma unroll
                for (int nt = 0; nt < 4; nt++) {
                    int col = wn + nt * 8 + 2 * fc;
                    float2 v;
                    v.x = acc[mt][nt][i2*2+0];
                    v.y = acc[mt][nt][i2*2+1];
                    *(float2*)(op + col) = v;
                }
            }
        }
    }
}

// ---------------- combine ----------------
__global__ void __launch_bounds__(256) combine_kernel(
    float* __restrict__ out, const float* __restrict__ shared_gate)
{
    const int idx = blockIdx.x * 256 + threadIdx.x;
    const float sig = 1.f / (1.f + expf(-shared_gate[0]));
    const int t = idx >> 10;
    const int h = idx & (H_DIM - 1);
    out[idx] = g_eout[(size_t)(2 * t) * H_DIM + h]
             + g_eout[(size_t)(2 * t + 1) * H_DIM + h]
             + g_shout[idx] * sig;
}

// ---------------- aux z-loss ----------------
__global__ void __launch_bounds__(256) aux_kernel(float* __restrict__ out)
{
    __shared__ float red[256];
    const int tid = threadIdx.x;
    float s = 0.f;
    for (int i = tid; i < T_TOK; i += 256) s += g_zsq[i];
    red[tid] = s;
    __syncthreads();
    for (int o = 128; o; o >>= 1) {
        if (tid < o) red[tid] += red[tid + o];
        __syncthreads();
    }
    if (tid == 0) out[(size_t)T_TOK * H_DIM] = red[0] * (1e-4f / T_TOK);
}

// ---------------- launch ----------------
extern "C" void kernel_launch(void* const* d_in, const int* in_sizes, int n_in,
                              void* d_out, int out_size)
{
    const float* x      = (const float*)d_in[0];
    const float* ln_g   = (const float*)d_in[1];
    const float* ln_b   = (const float*)d_in[2];
    const float* gate_w = (const float*)d_in[3];
    const float* bias   = (const float*)d_in[4];
    const float* Wg     = (const float*)d_in[5];
    const float* Wu     = (const float*)d_in[6];
    const float* Wd     = (const float*)d_in[7];
    const float* sh_g   = (const float*)d_in[8];
    const float* sh_b   = (const float*)d_in[9];
    const float* sWg    = (const float*)d_in[10];
    const float* sWu    = (const float*)d_in[11];
    const float* sWd    = (const float*)d_in[12];
    const float* sgate  = (const float*)d_in[13];
    float* out = (float*)d_out;

    zero_cnt_kernel<<<1, 32>>>();
    router_kernel<<<T_TOK, 256>>>(x, ln_g, ln_b, gate_w, bias, sh_g, sh_b);

    dim3 gu_grid(T_TOK / BM, I_DIM / BN, N_EXP);
    gemm_gateup<<<gu_grid, 256>>>(x, Wg, Wu, 1);
    dim3 gus_grid(T_TOK / BM, I_DIM / BN, 1);
    gemm_gateup<<<gus_grid, 256>>>(nullptr, sWg, sWu, 0);

    dim3 dn_grid(T_TOK / BM, H_DIM / BN, N_EXP);
    gemm_down<<<dn_grid, 256>>>(Wd, 1);
    dim3 dns_grid(T_TOK / BM, H_DIM / BN, 1);
    gemm_down<<<dns_grid, 256>>>(sWd, 0);

    combine_kernel<<<(T_TOK * H_DIM) / 256, 256>>>(out, sgate);
    aux_kernel<<<1, 256>>>(out);
}

// round 4
// speedup vs baseline: 2.2757x; 1.0443x over previous
#include <cuda_runtime.h>
#include <cuda_fp16.h>
#include <stdint.h>
#include <math.h>

// Problem constants
#define T_TOK 4096
#define H_DIM 1024
#define I_DIM 2048
#define N_EXP 8

// ---------------- scratch (static device globals; no allocs) ----------------
__device__ float  g_xs[(size_t)T_TOK * H_DIM];           // shared-expert LN(x)
__device__ int    g_cnt[N_EXP];
__device__ int    g_tok[N_EXP][T_TOK];
__device__ float  g_wt [N_EXP][T_TOK];
__device__ int    g_slot[N_EXP][T_TOK];                  // output slot = 2*t + rank
__device__ __half g_hidden[(size_t)2 * T_TOK * I_DIM];   // routed SwiGLU hidden (half)
__device__ float  g_eout [(size_t)2 * T_TOK * H_DIM];    // routed expert out
__device__ __half g_shid [(size_t)T_TOK * I_DIM];        // shared hidden (half)
__device__ float  g_shout[(size_t)T_TOK * H_DIM];        // shared out
__device__ float  g_zsq[T_TOK];

// ---------------- zero counters ----------------
__global__ void zero_cnt_kernel() {
    if (threadIdx.x < N_EXP) g_cnt[threadIdx.x] = 0;
}

// ---------------- router ----------------
__global__ void __launch_bounds__(256) router_kernel(
    const float* __restrict__ x,
    const float* __restrict__ ln_g, const float* __restrict__ ln_b,
    const float* __restrict__ gate_w, const float* __restrict__ bias,
    const float* __restrict__ sh_g, const float* __restrict__ sh_b)
{
    __shared__ float sx[H_DIM];
    __shared__ float sred[8], sred2[8];
    __shared__ float s_mean, s_rstd;
    __shared__ float logits[N_EXP];

    const int t   = blockIdx.x;
    const int tid = threadIdx.x;
    const float* xr = x + (size_t)t * H_DIM;

    float s = 0.f, s2 = 0.f;
#pragma unroll
    for (int i = 0; i < H_DIM / 256; i++) {
        float v = xr[tid + i * 256];
        sx[tid + i * 256] = v;
        s += v; s2 += v * v;
    }
#pragma unroll
    for (int o = 16; o; o >>= 1) {
        s  += __shfl_xor_sync(0xffffffffu, s,  o);
        s2 += __shfl_xor_sync(0xffffffffu, s2, o);
    }
    const int wid = tid >> 5, lane = tid & 31;
    if (lane == 0) { sred[wid] = s; sred2[wid] = s2; }
    __syncthreads();
    if (tid == 0) {
        float a = 0.f, b = 0.f;
        for (int i = 0; i < 8; i++) { a += sred[i]; b += sred2[i]; }
        float mean = a * (1.f / H_DIM);
        float var  = b * (1.f / H_DIM) - mean * mean;
        s_mean = mean;
        s_rstd = rsqrtf(var + 1e-5f);
    }
    __syncthreads();
    const float mean = s_mean, rstd = s_rstd;

    {
        const float* gw = gate_w + wid * H_DIM;
        float acc = 0.f;
        for (int i = lane; i < H_DIM; i += 32) {
            float hn = (sx[i] - mean) * rstd * ln_g[i] + ln_b[i];
            acc += hn * gw[i];
        }
#pragma unroll
        for (int o = 16; o; o >>= 1) acc += __shfl_xor_sync(0xffffffffu, acc, o);
        if (lane == 0) logits[wid] = acc + bias[wid];
    }

#pragma unroll
    for (int i = 0; i < H_DIM / 256; i++) {
        int idx = tid + i * 256;
        g_xs[(size_t)t * H_DIM + idx] = (sx[idx] - mean) * rstd * sh_g[idx] + sh_b[idx];
    }
    __syncthreads();

    if (tid == 0) {
        float mx = logits[0];
#pragma unroll
        for (int e = 1; e < N_EXP; e++) mx = fmaxf(mx, logits[e]);
        float p[N_EXP]; float se = 0.f;
#pragma unroll
        for (int e = 0; e < N_EXP; e++) { p[e] = expf(logits[e] - mx); se += p[e]; }
        float z = mx + logf(se);
        g_zsq[t] = z * z;
        int e1 = 0;
#pragma unroll
        for (int e = 1; e < N_EXP; e++) if (p[e] > p[e1]) e1 = e;
        int e2 = (e1 == 0) ? 1 : 0;
#pragma unroll
        for (int e = 0; e < N_EXP; e++) if (e != e1 && p[e] > p[e2]) e2 = e;
        float inv = 1.f / se;
        float p1 = p[e1] * inv, p2 = p[e2] * inv;
        float sm = fmaxf(p1 + p2, 1e-5f);
        int pos = atomicAdd(&g_cnt[e1], 1);
        g_tok[e1][pos] = t; g_wt[e1][pos] = p1 / sm; g_slot[e1][pos] = 2 * t;
        pos = atomicAdd(&g_cnt[e2], 1);
        g_tok[e2][pos] = t; g_wt[e2][pos] = p2 / sm; g_slot[e2][pos] = 2 * t + 1;
    }
}

// ---------------- tensor-core GEMMs ----------------
#define BM 128
#define BN 64
#define BK 32
// smem rows are 80B (5 uint4): (5r+c) mod 8 is a permutation in r -> ldmatrix
// phases and STS.128 phases are bank-conflict-free with no XOR swizzle.

#define MMA16816(d, a, b) \
  asm volatile("mma.sync.aligned.m16n8k16.row.col.f32.f16.f16.f32 " \
    "{%0,%1,%2,%3}, {%4,%5,%6,%7}, {%8,%9}, {%0,%1,%2,%3};" \
    : "+f"((d)[0]), "+f"((d)[1]), "+f"((d)[2]), "+f"((d)[3]) \
    : "r"((a)[0]), "r"((a)[1]), "r"((a)[2]), "r"((a)[3]), "r"((b)[0]), "r"((b)[1]))

#define LDSM4(r0, r1, r2, r3, addr) \
  asm volatile("ldmatrix.sync.aligned.m8n8.x4.shared.b16 {%0,%1,%2,%3}, [%4];" \
    : "=r"(r0), "=r"(r1), "=r"(r2), "=r"(r3) : "r"(addr))

__device__ __forceinline__ uint32_t h2u(half2 h) { return *(uint32_t*)&h; }
__device__ __forceinline__ uint32_t smem_u32(const void* p) {
    return (uint32_t)__cvta_generic_to_shared(p);
}
__device__ __forceinline__ uint4 cvt8(float4 a, float4 b) {
    uint4 r;
    r.x = h2u(__floats2half2_rn(a.x, a.y));
    r.y = h2u(__floats2half2_rn(a.z, a.w));
    r.z = h2u(__floats2half2_rn(b.x, b.y));
    r.w = h2u(__floats2half2_rn(b.z, b.w));
    return r;
}

// fused gate/up GEMM + SwiGLU  (A fp32 gathered rows, B fp32 weights)
__global__ void __launch_bounds__(256) gemm_gateup(
    const float* __restrict__ x_routed,
    const float* __restrict__ Wg_all,
    const float* __restrict__ Wu_all,
    int routed)
{
    const int e = blockIdx.z;
    const int cnt = routed ? g_cnt[e] : T_TOK;
    const int m0 = blockIdx.x * BM;
    if (m0 >= cnt) return;
    const int n0 = blockIdx.y * BN;

    const float* xsrc = routed ? x_routed : g_xs;
    __half* hid       = routed ? g_hidden : g_shid;
    const float* Wg = Wg_all + (size_t)e * I_DIM * H_DIM;
    const float* Wu = Wu_all + (size_t)e * I_DIM * H_DIM;

    __shared__ uint4 As [2][BM][5];   // 128 rows x 80B
    __shared__ uint4 Bgs[2][BN][5];   //  64 rows x 80B
    __shared__ uint4 Bus[2][BN][5];

    const int tid  = threadIdx.x;
    const int lane = tid & 31;
    const int wid  = tid >> 5;
    const int wm   = (wid & 3) * 32;
    const int wn   = (wid >> 2) * 32;
    const int fr   = lane >> 2;
    const int fc   = lane & 3;

    // staging maps
    const int arow = tid & 127;
    const int ach  = tid >> 7;            // {0,1} -> chunks 2ach, 2ach+1 (k floats 16ach..+16)
    const float* aptr = nullptr;
    if (m0 + arow < cnt) {
        int r = routed ? g_tok[e][m0 + arow] : (m0 + arow);
        aptr = xsrc + (size_t)r * H_DIM;
    }
    const int brow = tid & 63;
    const int bc   = tid >> 6;            // {0..3} -> chunk bc (k floats 8bc..+8)
    const float* bgp = Wg + (size_t)(n0 + brow) * H_DIM;
    const float* bup = Wu + (size_t)(n0 + brow) * H_DIM;

    // ldmatrix lane offset: row = (l&7) + ((l>>3)&1)*8, 16B col = (l>>4)&1
    const uint32_t loff = (uint32_t)(((lane & 7) + ((lane >> 3) & 1) * 8) * 80
                                     + ((lane >> 4) & 1) * 16);
    const uint32_t As_b  = smem_u32(&As [0][0][0]);
    const uint32_t Bgs_b = smem_u32(&Bgs[0][0][0]);
    const uint32_t Bus_b = smem_u32(&Bus[0][0][0]);
    const uint32_t ASZ = BM * 80, BSZ = BN * 80;

    float acg[2][4][4] = {};
    float acu[2][4][4] = {};

    const int NC = H_DIM / BK;  // 32
    const float4 z4 = make_float4(0.f, 0.f, 0.f, 0.f);

    // prologue: chunk 0
    {
        float4 a0 = aptr ? *(const float4*)(aptr + 16 * ach)      : z4;
        float4 a1 = aptr ? *(const float4*)(aptr + 16 * ach + 4)  : z4;
        float4 a2 = aptr ? *(const float4*)(aptr + 16 * ach + 8)  : z4;
        float4 a3 = aptr ? *(const float4*)(aptr + 16 * ach + 12) : z4;
        float4 g0 = *(const float4*)(bgp + 8 * bc);
        float4 g1 = *(const float4*)(bgp + 8 * bc + 4);
        float4 u0 = *(const float4*)(bup + 8 * bc);
        float4 u1 = *(const float4*)(bup + 8 * bc + 4);
        As [0][arow][2 * ach]     = cvt8(a0, a1);
        As [0][arow][2 * ach + 1] = cvt8(a2, a3);
        Bgs[0][brow][bc] = cvt8(g0, g1);
        Bus[0][brow][bc] = cvt8(u0, u1);
    }
    __syncthreads();

    for (int c = 1; c <= NC; c++) {
        float4 a0, a1, a2, a3, rg0, rg1, ru0, ru1;
        if (c < NC) {
            const int k0 = c * BK;
            a0 = aptr ? *(const float4*)(aptr + k0 + 16 * ach)      : z4;
            a1 = aptr ? *(const float4*)(aptr + k0 + 16 * ach + 4)  : z4;
            a2 = aptr ? *(const float4*)(aptr + k0 + 16 * ach + 8)  : z4;
            a3 = aptr ? *(const float4*)(aptr + k0 + 16 * ach + 12) : z4;
            rg0 = *(const float4*)(bgp + k0 + 8 * bc);
            rg1 = *(const float4*)(bgp + k0 + 8 * bc + 4);
            ru0 = *(const float4*)(bup + k0 + 8 * bc);
            ru1 = *(const float4*)(bup + k0 + 8 * bc + 4);
        }
        const int pb = (c + 1) & 1;
        const uint32_t Ab  = As_b  + pb * ASZ + loff;
        const uint32_t Bgb = Bgs_b + pb * BSZ + loff;
        const uint32_t Bub = Bus_b + pb * BSZ + loff;
#pragma unroll
        for (int s = 0; s < 2; s++) {
            uint32_t a[2][4];
#pragma unroll
            for (int mt = 0; mt < 2; mt++)
                LDSM4(a[mt][0], a[mt][1], a[mt][2], a[mt][3],
                      Ab + (wm + mt * 16) * 80 + s * 32);
            uint32_t bg[4][2], bu[4][2];
#pragma unroll
            for (int np = 0; np < 2; np++) {
                uint32_t q0, q1, q2, q3;
                LDSM4(q0, q1, q2, q3, Bgb + (wn + np * 16) * 80 + s * 32);
                bg[2*np][0] = q0; bg[2*np][1] = q2;
                bg[2*np+1][0] = q1; bg[2*np+1][1] = q3;
                LDSM4(q0, q1, q2, q3, Bub + (wn + np * 16) * 80 + s * 32);
                bu[2*np][0] = q0; bu[2*np][1] = q2;
                bu[2*np+1][0] = q1; bu[2*np+1][1] = q3;
            }
#pragma unroll
            for (int mt = 0; mt < 2; mt++)
#pragma unroll
                for (int nt = 0; nt < 4; nt++) {
                    MMA16816(acg[mt][nt], a[mt], bg[nt]);
                    MMA16816(acu[mt][nt], a[mt], bu[nt]);
                }
        }
        if (c < NC) {
            const int cb = c & 1;
            As [cb][arow][2 * ach]     = cvt8(a0, a1);
            As [cb][arow][2 * ach + 1] = cvt8(a2, a3);
            Bgs[cb][brow][bc] = cvt8(rg0, rg1);
            Bus[cb][brow][bc] = cvt8(ru0, ru1);
            __syncthreads();
        }
    }

    // epilogue: silu(g)*u -> half
#pragma unroll
    for (int mt = 0; mt < 2; mt++) {
#pragma unroll
        for (int i2 = 0; i2 < 2; i2++) {
            int row = wm + mt * 16 + fr + i2 * 8;
            int m = m0 + row;
            if (m >= cnt) continue;
            int orow = routed ? g_slot[e][m] : m;
            __half* op = hid + (size_t)orow * I_DIM + n0;
#pragma unroll
            for (int nt = 0; nt < 4; nt++) {
                int col = wn + nt * 8 + 2 * fc;
                float g0 = acg[mt][nt][i2*2+0], g1 = acg[mt][nt][i2*2+1];
                float u0 = acu[mt][nt][i2*2+0], u1 = acu[mt][nt][i2*2+1];
                float v0 = (g0 / (1.f + expf(-g0))) * u0;
                float v1 = (g1 / (1.f + expf(-g1))) * u1;
                *(half2*)(op + col) = __floats2half2_rn(v0, v1);
            }
        }
    }
}

// down GEMM (+ combine weight for routed); A is half hidden, B fp32 weights
__global__ void __launch_bounds__(256) gemm_down(
    const float* __restrict__ Wd_all,
    int routed)
{
    const int e = blockIdx.z;
    const int cnt = routed ? g_cnt[e] : T_TOK;
    const int m0 = blockIdx.x * BM;
    if (m0 >= cnt) return;
    const int n0 = blockIdx.y * BN;

    const __half* hid = routed ? g_hidden : g_shid;
    const float* Wd   = Wd_all + (size_t)e * H_DIM * I_DIM;

    __shared__ uint4 As[2][BM][5];
    __shared__ uint4 Bs[2][BN][5];

    const int tid  = threadIdx.x;
    const int lane = tid & 31;
    const int wid  = tid >> 5;
    const int wm   = (wid & 3) * 32;
    const int wn   = (wid >> 2) * 32;
    const int fr   = lane >> 2;
    const int fc   = lane & 3;

    const int arow = tid & 127;
    const int ach  = tid >> 7;            // halves [16ach, 16ach+16) of each BK window
    const __half* aptr = nullptr;
    if (m0 + arow < cnt) {
        int aslot = routed ? g_slot[e][m0 + arow] : (m0 + arow);
        aptr = hid + (size_t)aslot * I_DIM;
    }
    const int brow = tid & 63;
    const int bc   = tid >> 6;
    const float* bp = Wd + (size_t)(n0 + brow) * I_DIM;

    const uint32_t loff = (uint32_t)(((lane & 7) + ((lane >> 3) & 1) * 8) * 80
                                     + ((lane >> 4) & 1) * 16);
    const uint32_t As_b = smem_u32(&As[0][0][0]);
    const uint32_t Bs_b = smem_u32(&Bs[0][0][0]);
    const uint32_t ASZ = BM * 80, BSZ = BN * 80;

    float acc[2][4][4] = {};
    const int NC = I_DIM / BK;  // 64
    const uint4  zu = make_uint4(0u, 0u, 0u, 0u);
    const float4 z4 = make_float4(0.f, 0.f, 0.f, 0.f);

    {
        uint4 ha = aptr ? *(const uint4*)(aptr + 16 * ach)     : zu;
        uint4 hb = aptr ? *(const uint4*)(aptr + 16 * ach + 8) : zu;
        float4 b0 = *(const float4*)(bp + 8 * bc);
        float4 b1 = *(const float4*)(bp + 8 * bc + 4);
        As[0][arow][2 * ach]     = ha;
        As[0][arow][2 * ach + 1] = hb;
        Bs[0][brow][bc] = cvt8(b0, b1);
    }
    __syncthreads();

    for (int c = 1; c <= NC; c++) {
        uint4 ha, hb; float4 b0, b1;
        if (c < NC) {
            const int k0 = c * BK;
            ha = aptr ? *(const uint4*)(aptr + k0 + 16 * ach)     : zu;
            hb = aptr ? *(const uint4*)(aptr + k0 + 16 * ach + 8) : zu;
            b0 = *(const float4*)(bp + k0 + 8 * bc);
            b1 = *(const float4*)(bp + k0 + 8 * bc + 4);
        } else { ha = hb = zu; b0 = b1 = z4; }
        const int pb = (c + 1) & 1;
        const uint32_t Ab = As_b + pb * ASZ + loff;
        const uint32_t Bb = Bs_b + pb * BSZ + loff;
#pragma unroll
        for (int s = 0; s < 2; s++) {
            uint32_t a[2][4];
#pragma unroll
            for (int mt = 0; mt < 2; mt++)
                LDSM4(a[mt][0], a[mt][1], a[mt][2], a[mt][3],
                      Ab + (wm + mt * 16) * 80 + s * 32);
            uint32_t b[4][2];
#pragma unroll
            for (int np = 0; np < 2; np++) {
                uint32_t q0, q1, q2, q3;
                LDSM4(q0, q1, q2, q3, Bb + (wn + np * 16) * 80 + s * 32);
                b[2*np][0] = q0; b[2*np][1] = q2;
                b[2*np+1][0] = q1; b[2*np+1][1] = q3;
            }
#pragma unroll
            for (int mt = 0; mt < 2; mt++)
#pragma unroll
                for (int nt = 0; nt < 4; nt++)
                    MMA16816(acc[mt][nt], a[mt], b[nt]);
        }
        if (c < NC) {
            const int cb = c & 1;
            As[cb][arow][2 * ach]     = ha;
            As[cb][arow][2 * ach + 1] = hb;
            Bs[cb][brow][bc] = cvt8(b0, b1);
            __syncthreads();
        }
    }

#pragma unroll
    for (int mt = 0; mt < 2; mt++) {
#pragma unroll
        for (int i2 = 0; i2 < 2; i2++) {
            int row = wm + mt * 16 + fr + i2 * 8;
            int m = m0 + row;
            if (m >= cnt) continue;
            if (routed) {
                int orow = g_slot[e][m];
                float w  = g_wt[e][m];
                float* op = g_eout + (size_t)orow * H_DIM + n0;
#pragma unroll
                for (int nt = 0; nt < 4; nt++) {
                    int col = wn + nt * 8 + 2 * fc;
                    float2 v;
                    v.x = acc[mt][nt][i2*2+0] * w;
                    v.y = acc[mt][nt][i2*2+1] * w;
                    *(float2*)(op + col) = v;
                }
            } else {
                float* op = g_shout + (size_t)m * H_DIM + n0;
#pragma unroll
                for (int nt = 0; nt < 4; nt++) {
                    int col = wn + nt * 8 + 2 * fc;
                    float2 v;
                    v.x = acc[mt][nt][i2*2+0];
                    v.y = acc[mt][nt][i2*2+1];
                    *(float2*)(op + col) = v;
                }
            }
        }
    }
}

// ---------------- combine ----------------
__global__ void __launch_bounds__(256) combine_kernel(
    float* __restrict__ out, const float* __restrict__ shared_gate)
{
    const int idx = blockIdx.x * 256 + threadIdx.x;
    const float sig = 1.f / (1.f + expf(-shared_gate[0]));
    const int t = idx >> 10;
    const int h = idx & (H_DIM - 1);
    out[idx] = g_eout[(size_t)(2 * t) * H_DIM + h]
             + g_eout[(size_t)(2 * t + 1) * H_DIM + h]
             + g_shout[idx] * sig;
}

// ---------------- aux z-loss ----------------
__global__ void __launch_bounds__(256) aux_kernel(float* __restrict__ out)
{
    __shared__ float red[256];
    const int tid = threadIdx.x;
    float s = 0.f;
    for (int i = tid; i < T_TOK; i += 256) s += g_zsq[i];
    red[tid] = s;
    __syncthreads();
    for (int o = 128; o; o >>= 1) {
        if (tid < o) red[tid] += red[tid + o];
        __syncthreads();
    }
    if (tid == 0) out[(size_t)T_TOK * H_DIM] = red[0] * (1e-4f / T_TOK);
}

// ---------------- launch ----------------
extern "C" void kernel_launch(void* const* d_in, const int* in_sizes, int n_in,
                              void* d_out, int out_size)
{
    const float* x      = (const float*)d_in[0];
    const float* ln_g   = (const float*)d_in[1];
    const float* ln_b   = (const float*)d_in[2];
    const float* gate_w = (const float*)d_in[3];
    const float* bias   = (const float*)d_in[4];
    const float* Wg     = (const float*)d_in[5];
    const float* Wu     = (const float*)d_in[6];
    const float* Wd     = (const float*)d_in[7];
    const float* sh_g   = (const float*)d_in[8];
    const float* sh_b   = (const float*)d_in[9];
    const float* sWg    = (const float*)d_in[10];
    const float* sWu    = (const float*)d_in[11];
    const float* sWd    = (const float*)d_in[12];
    const float* sgate  = (const float*)d_in[13];
    float* out = (float*)d_out;

    zero_cnt_kernel<<<1, 32>>>();
    router_kernel<<<T_TOK, 256>>>(x, ln_g, ln_b, gate_w, bias, sh_g, sh_b);

    dim3 gu_grid(T_TOK / BM, I_DIM / BN, N_EXP);
    gemm_gateup<<<gu_grid, 256>>>(x, Wg, Wu, 1);
    dim3 gus_grid(T_TOK / BM, I_DIM / BN, 1);
    gemm_gateup<<<gus_grid, 256>>>(nullptr, sWg, sWu, 0);

    dim3 dn_grid(T_TOK / BM, H_DIM / BN, N_EXP);
    gemm_down<<<dn_grid, 256>>>(Wd, 1);
    dim3 dns_grid(T_TOK / BM, H_DIM / BN, 1);
    gemm_down<<<dns_grid, 256>>>(sWd, 0);

    combine_kernel<<<(T_TOK * H_DIM) / 256, 256>>>(out, sgate);
    aux_kernel<<<1, 256>>>(out);
}

// round 5
// speedup vs baseline: 3.9938x; 1.7549x over previous
#include <cuda_runtime.h>
#include <cuda_fp16.h>
#include <stdint.h>
#include <math.h>

// Problem constants
#define T_TOK 4096
#define H_DIM 1024
#define I_DIM 2048
#define N_EXP 8

// ---------------- scratch (static device globals; no allocs) ----------------
__device__ int    g_cnt[N_EXP];
__device__ int    g_tok[N_EXP][T_TOK];
__device__ float  g_wt [N_EXP][T_TOK];
__device__ int    g_slot[N_EXP][T_TOK];                  // output slot = 2*t + rank
__device__ __half g_hidden[(size_t)2 * T_TOK * I_DIM];   // routed SwiGLU hidden
__device__ float  g_eout [(size_t)2 * T_TOK * H_DIM];    // routed expert out
__device__ __half g_shid [(size_t)T_TOK * I_DIM];        // shared hidden
__device__ float  g_shout[(size_t)T_TOK * H_DIM];        // shared out
__device__ float  g_zsq[T_TOK];

// fp16 copies (pre-converted once per launch)
__device__ __half g_xh  [(size_t)T_TOK * H_DIM];             // x as half
__device__ __half g_xsh [(size_t)T_TOK * H_DIM];             // shared-LN(x) as half
__device__ __half g_hWg [(size_t)N_EXP * I_DIM * H_DIM];
__device__ __half g_hWu [(size_t)N_EXP * I_DIM * H_DIM];
__device__ __half g_hWd [(size_t)N_EXP * H_DIM * I_DIM];
__device__ __half g_hsWg[(size_t)I_DIM * H_DIM];
__device__ __half g_hsWu[(size_t)I_DIM * H_DIM];
__device__ __half g_hsWd[(size_t)H_DIM * I_DIM];

__device__ __forceinline__ uint32_t h2u(half2 h) { return *(uint32_t*)&h; }
__device__ __forceinline__ uint32_t smem_u32(const void* p) {
    return (uint32_t)__cvta_generic_to_shared(p);
}
__device__ __forceinline__ uint4 cvt8(float4 a, float4 b) {
    uint4 r;
    r.x = h2u(__floats2half2_rn(a.x, a.y));
    r.y = h2u(__floats2half2_rn(a.z, a.w));
    r.z = h2u(__floats2half2_rn(b.x, b.y));
    r.w = h2u(__floats2half2_rn(b.z, b.w));
    return r;
}

// ---------------- fp32 -> fp16 convert (8 elems/thread) ----------------
__global__ void __launch_bounds__(256) cvt_f2h(
    const float* __restrict__ src, __half* __restrict__ dst, int n8)
{
    int i = blockIdx.x * 256 + threadIdx.x;
    if (i >= n8) return;
    float4 a = ((const float4*)src)[2 * i];
    float4 b = ((const float4*)src)[2 * i + 1];
    ((uint4*)dst)[i] = cvt8(a, b);
}

// ---------------- zero counters ----------------
__global__ void zero_cnt_kernel() {
    if (threadIdx.x < N_EXP) g_cnt[threadIdx.x] = 0;
}

// ---------------- router ----------------
__global__ void __launch_bounds__(256) router_kernel(
    const float* __restrict__ x,
    const float* __restrict__ ln_g, const float* __restrict__ ln_b,
    const float* __restrict__ gate_w, const float* __restrict__ bias,
    const float* __restrict__ sh_g, const float* __restrict__ sh_b)
{
    __shared__ float sx[H_DIM];
    __shared__ float sred[8], sred2[8];
    __shared__ float s_mean, s_rstd;
    __shared__ float logits[N_EXP];

    const int t   = blockIdx.x;
    const int tid = threadIdx.x;
    const float* xr = x + (size_t)t * H_DIM;

    float s = 0.f, s2 = 0.f;
#pragma unroll
    for (int i = 0; i < H_DIM / 256; i++) {
        float v = xr[tid + i * 256];
        sx[tid + i * 256] = v;
        s += v; s2 += v * v;
    }
#pragma unroll
    for (int o = 16; o; o >>= 1) {
        s  += __shfl_xor_sync(0xffffffffu, s,  o);
        s2 += __shfl_xor_sync(0xffffffffu, s2, o);
    }
    const int wid = tid >> 5, lane = tid & 31;
    if (lane == 0) { sred[wid] = s; sred2[wid] = s2; }
    __syncthreads();
    if (tid == 0) {
        float a = 0.f, b = 0.f;
        for (int i = 0; i < 8; i++) { a += sred[i]; b += sred2[i]; }
        float mean = a * (1.f / H_DIM);
        float var  = b * (1.f / H_DIM) - mean * mean;
        s_mean = mean;
        s_rstd = rsqrtf(var + 1e-5f);
    }
    __syncthreads();
    const float mean = s_mean, rstd = s_rstd;

    {
        const float* gw = gate_w + wid * H_DIM;
        float acc = 0.f;
        for (int i = lane; i < H_DIM; i += 32) {
            float hn = (sx[i] - mean) * rstd * ln_g[i] + ln_b[i];
            acc += hn * gw[i];
        }
#pragma unroll
        for (int o = 16; o; o >>= 1) acc += __shfl_xor_sync(0xffffffffu, acc, o);
        if (lane == 0) logits[wid] = acc + bias[wid];
    }

    // shared-expert LN -> half
#pragma unroll
    for (int i = 0; i < H_DIM / 256; i++) {
        int idx = tid + i * 256;
        float v = (sx[idx] - mean) * rstd * sh_g[idx] + sh_b[idx];
        g_xsh[(size_t)t * H_DIM + idx] = __float2half_rn(v);
    }
    __syncthreads();

    if (tid == 0) {
        float mx = logits[0];
#pragma unroll
        for (int e = 1; e < N_EXP; e++) mx = fmaxf(mx, logits[e]);
        float p[N_EXP]; float se = 0.f;
#pragma unroll
        for (int e = 0; e < N_EXP; e++) { p[e] = expf(logits[e] - mx); se += p[e]; }
        float z = mx + logf(se);
        g_zsq[t] = z * z;
        int e1 = 0;
#pragma unroll
        for (int e = 1; e < N_EXP; e++) if (p[e] > p[e1]) e1 = e;
        int e2 = (e1 == 0) ? 1 : 0;
#pragma unroll
        for (int e = 0; e < N_EXP; e++) if (e != e1 && p[e] > p[e2]) e2 = e;
        float inv = 1.f / se;
        float p1 = p[e1] * inv, p2 = p[e2] * inv;
        float sm = fmaxf(p1 + p2, 1e-5f);
        int pos = atomicAdd(&g_cnt[e1], 1);
        g_tok[e1][pos] = t; g_wt[e1][pos] = p1 / sm; g_slot[e1][pos] = 2 * t;
        pos = atomicAdd(&g_cnt[e2], 1);
        g_tok[e2][pos] = t; g_wt[e2][pos] = p2 / sm; g_slot[e2][pos] = 2 * t + 1;
    }
}

// ---------------- tensor-core GEMMs ----------------
#define BM 128
#define BN 64
#define BK 32
#define NSTAGE 4
// smem rows are 80B (5 uint4): data in first 64B (32 halves), 16B pad.
// (r*80/16) mod 8 = 5r mod 8 is a permutation -> ldmatrix phases conflict-free.
#define GU_STAGE 20480     // A 128*80 + Bg 64*80 + Bu 64*80
#define GU_BG_OFF 10240
#define GU_BU_OFF 15360
#define DN_STAGE 15360     // A 128*80 + B 64*80
#define DN_B_OFF 10240

#define MMA16816(d, a, b) \
  asm volatile("mma.sync.aligned.m16n8k16.row.col.f32.f16.f16.f32 " \
    "{%0,%1,%2,%3}, {%4,%5,%6,%7}, {%8,%9}, {%0,%1,%2,%3};" \
    : "+f"((d)[0]), "+f"((d)[1]), "+f"((d)[2]), "+f"((d)[3]) \
    : "r"((a)[0]), "r"((a)[1]), "r"((a)[2]), "r"((a)[3]), "r"((b)[0]), "r"((b)[1]))

#define LDSM4(r0, r1, r2, r3, addr) \
  asm volatile("ldmatrix.sync.aligned.m8n8.x4.shared.b16 {%0,%1,%2,%3}, [%4];" \
    : "=r"(r0), "=r"(r1), "=r"(r2), "=r"(r3) : "r"(addr))

#define CPA16(dst, src, sz) \
  asm volatile("cp.async.cg.shared.global [%0], [%1], 16, %2;" \
    :: "r"(dst), "l"(src), "r"(sz))
#define CPCOMMIT() asm volatile("cp.async.commit_group;")
#define CPWAIT(n)  asm volatile("cp.async.wait_group %0;" :: "n"(n))

// fused gate/up GEMM + SwiGLU (all-half operands)
__global__ void __launch_bounds__(256) gemm_gateup(
    const __half* __restrict__ xh,
    const __half* __restrict__ Wg_all,
    const __half* __restrict__ Wu_all,
    int routed)
{
    extern __shared__ uint8_t dsm[];
    const int e = blockIdx.z;
    const int cnt = routed ? g_cnt[e] : T_TOK;
    const int m0 = blockIdx.x * BM;
    if (m0 >= cnt) return;
    const int n0 = blockIdx.y * BN;

    __half* hid = routed ? g_hidden : g_shid;
    const __half* Wg = Wg_all + (size_t)e * I_DIM * H_DIM;
    const __half* Wu = Wu_all + (size_t)e * I_DIM * H_DIM;

    const int tid  = threadIdx.x;
    const int lane = tid & 31;
    const int wid  = tid >> 5;
    const int wm   = (wid & 3) * 32;
    const int wn   = (wid >> 2) * 32;
    const int fr   = lane >> 2;
    const int fc   = lane & 3;

    // load maps
    const int arow = tid & 127;
    const int apair = tid >> 7;            // segs {2a,2a+1} of 4x16B per row-chunk
    const __half* aptr = xh;               // valid dummy when OOB
    uint32_t apred = 0;
    if (m0 + arow < cnt) {
        int r = routed ? g_tok[e][m0 + arow] : (m0 + arow);
        aptr = xh + (size_t)r * H_DIM;
        apred = 16u;
    }
    const int brow = tid & 63;
    const int bseg = tid >> 6;             // {0..3}
    const __half* bgp = Wg + (size_t)(n0 + brow) * H_DIM;
    const __half* bup = Wu + (size_t)(n0 + brow) * H_DIM;

    const uint32_t sb = smem_u32(dsm);
    const uint32_t adst  = sb + arow * 80 + apair * 32;
    const uint32_t bgdst = sb + GU_BG_OFF + brow * 80 + bseg * 16;
    const uint32_t budst = sb + GU_BU_OFF + brow * 80 + bseg * 16;
    const uint32_t loff = (uint32_t)(((lane & 7) + ((lane >> 3) & 1) * 8) * 80
                                     + ((lane >> 4) & 1) * 16);

    float acg[2][4][4] = {};
    float acu[2][4][4] = {};
    const int NC = H_DIM / BK;  // 32

#define GU_ISSUE(c) do { \
    uint32_t st_ = (uint32_t)((c) & (NSTAGE - 1)) * GU_STAGE; \
    const __half* as_ = aptr + (c) * BK + apair * 16; \
    CPA16(adst + st_,       as_,     apred); \
    CPA16(adst + st_ + 16,  as_ + 8, apred); \
    CPA16(bgdst + st_, bgp + (c) * BK + bseg * 8, 16u); \
    CPA16(budst + st_, bup + (c) * BK + bseg * 8, 16u); \
} while (0)

#pragma unroll
    for (int s = 0; s < NSTAGE - 1; s++) { GU_ISSUE(s); CPCOMMIT(); }

    for (int c = 0; c < NC; c++) {
        CPWAIT(NSTAGE - 2);
        __syncthreads();
        const uint32_t st = (uint32_t)(c & (NSTAGE - 1)) * GU_STAGE;
        const uint32_t Ab  = sb + st + loff;
        const uint32_t Bgb = sb + st + GU_BG_OFF + loff;
        const uint32_t Bub = sb + st + GU_BU_OFF + loff;
#pragma unroll
        for (int s = 0; s < 2; s++) {
            uint32_t a[2][4];
#pragma unroll
            for (int mt = 0; mt < 2; mt++)
                LDSM4(a[mt][0], a[mt][1], a[mt][2], a[mt][3],
                      Ab + (wm + mt * 16) * 80 + s * 32);
            uint32_t bg[4][2], bu[4][2];
#pragma unroll
            for (int np = 0; np < 2; np++) {
                uint32_t q0, q1, q2, q3;
                LDSM4(q0, q1, q2, q3, Bgb + (wn + np * 16) * 80 + s * 32);
                bg[2*np][0] = q0; bg[2*np][1] = q2;
                bg[2*np+1][0] = q1; bg[2*np+1][1] = q3;
                LDSM4(q0, q1, q2, q3, Bub + (wn + np * 16) * 80 + s * 32);
                bu[2*np][0] = q0; bu[2*np][1] = q2;
                bu[2*np+1][0] = q1; bu[2*np+1][1] = q3;
            }
#pragma unroll
            for (int mt = 0; mt < 2; mt++)
#pragma unroll
                for (int nt = 0; nt < 4; nt++) {
                    MMA16816(acg[mt][nt], a[mt], bg[nt]);
                    MMA16816(acu[mt][nt], a[mt], bu[nt]);
                }
        }
        __syncthreads();
        if (c + NSTAGE - 1 < NC) GU_ISSUE(c + NSTAGE - 1);
        CPCOMMIT();
    }

    // epilogue: silu(g)*u -> half
#pragma unroll
    for (int mt = 0; mt < 2; mt++) {
#pragma unroll
        for (int i2 = 0; i2 < 2; i2++) {
            int row = wm + mt * 16 + fr + i2 * 8;
            int m = m0 + row;
            if (m >= cnt) continue;
            int orow = routed ? g_slot[e][m] : m;
            __half* op = hid + (size_t)orow * I_DIM + n0;
#pragma unroll
            for (int nt = 0; nt < 4; nt++) {
                int col = wn + nt * 8 + 2 * fc;
                float g0 = acg[mt][nt][i2*2+0], g1 = acg[mt][nt][i2*2+1];
                float u0 = acu[mt][nt][i2*2+0], u1 = acu[mt][nt][i2*2+1];
                float v0 = (g0 / (1.f + expf(-g0))) * u0;
                float v1 = (g1 / (1.f + expf(-g1))) * u1;
                *(half2*)(op + col) = __floats2half2_rn(v0, v1);
            }
        }
    }
}

// down GEMM (+ combine weight for routed); all-half operands
__global__ void __launch_bounds__(256) gemm_down(
    const __half* __restrict__ Wd_all,
    int routed)
{
    extern __shared__ uint8_t dsm[];
    const int e = blockIdx.z;
    const int cnt = routed ? g_cnt[e] : T_TOK;
    const int m0 = blockIdx.x * BM;
    if (m0 >= cnt) return;
    const int n0 = blockIdx.y * BN;

    const __half* hid = routed ? g_hidden : g_shid;
    const __half* Wd  = Wd_all + (size_t)e * H_DIM * I_DIM;

    const int tid  = threadIdx.x;
    const int lane = tid & 31;
    const int wid  = tid >> 5;
    const int wm   = (wid & 3) * 32;
    const int wn   = (wid >> 2) * 32;
    const int fr   = lane >> 2;
    const int fc   = lane & 3;

    const int arow = tid & 127;
    const int apair = tid >> 7;
    const __half* aptr = hid;
    uint32_t apred = 0;
    if (m0 + arow < cnt) {
        int aslot = routed ? g_slot[e][m0 + arow] : (m0 + arow);
        aptr = hid + (size_t)aslot * I_DIM;
        apred = 16u;
    }
    const int brow = tid & 63;
    const int bseg = tid >> 6;
    const __half* bp = Wd + (size_t)(n0 + brow) * I_DIM;

    const uint32_t sb = smem_u32(dsm);
    const uint32_t adst = sb + arow * 80 + apair * 32;
    const uint32_t bdst = sb + DN_B_OFF + brow * 80 + bseg * 16;
    const uint32_t loff = (uint32_t)(((lane & 7) + ((lane >> 3) & 1) * 8) * 80
                                     + ((lane >> 4) & 1) * 16);

    float acc[2][4][4] = {};
    const int NC = I_DIM / BK;  // 64

#define DN_ISSUE(c) do { \
    uint32_t st_ = (uint32_t)((c) & (NSTAGE - 1)) * DN_STAGE; \
    const __half* as_ = aptr + (c) * BK + apair * 16; \
    CPA16(adst + st_,       as_,     apred); \
    CPA16(adst + st_ + 16,  as_ + 8, apred); \
    CPA16(bdst + st_, bp + (c) * BK + bseg * 8, 16u); \
} while (0)

#pragma unroll
    for (int s = 0; s < NSTAGE - 1; s++) { DN_ISSUE(s); CPCOMMIT(); }

    for (int c = 0; c < NC; c++) {
        CPWAIT(NSTAGE - 2);
        __syncthreads();
        const uint32_t st = (uint32_t)(c & (NSTAGE - 1)) * DN_STAGE;
        const uint32_t Ab = sb + st + loff;
        const uint32_t Bb = sb + st + DN_B_OFF + loff;
#pragma unroll
        for (int s = 0; s < 2; s++) {
            uint32_t a[2][4];
#pragma unroll
            for (int mt = 0; mt < 2; mt++)
                LDSM4(a[mt][0], a[mt][1], a[mt][2], a[mt][3],
                      Ab + (wm + mt * 16) * 80 + s * 32);
            uint32_t b[4][2];
#pragma unroll
            for (int np = 0; np < 2; np++) {
                uint32_t q0, q1, q2, q3;
                LDSM4(q0, q1, q2, q3, Bb + (wn + np * 16) * 80 + s * 32);
                b[2*np][0] = q0; b[2*np][1] = q2;
                b[2*np+1][0] = q1; b[2*np+1][1] = q3;
            }
#pragma unroll
            for (int mt = 0; mt < 2; mt++)
#pragma unroll
                for (int nt = 0; nt < 4; nt++)
                    MMA16816(acc[mt][nt], a[mt], b[nt]);
        }
        __syncthreads();
        if (c + NSTAGE - 1 < NC) DN_ISSUE(c + NSTAGE - 1);
        CPCOMMIT();
    }

#pragma unroll
    for (int mt = 0; mt < 2; mt++) {
#pragma unroll
        for (int i2 = 0; i2 < 2; i2++) {
            int row = wm + mt * 16 + fr + i2 * 8;
            int m = m0 + row;
            if (m >= cnt) continue;
            if (routed) {
                int orow = g_slot[e][m];
                float w  = g_wt[e][m];
                float* op = g_eout + (size_t)orow * H_DIM + n0;
#pragma unroll
                for (int nt = 0; nt < 4; nt++) {
                    int col = wn + nt * 8 + 2 * fc;
                    float2 v;
                    v.x = acc[mt][nt][i2*2+0] * w;
                    v.y = acc[mt][nt][i2*2+1] * w;
                    *(float2*)(op + col) = v;
                }
            } else {
                float* op = g_shout + (size_t)m * H_DIM + n0;
#pragma unroll
                for (int nt = 0; nt < 4; nt++) {
                    int col = wn + nt * 8 + 2 * fc;
                    float2 v;
                    v.x = acc[mt][nt][i2*2+0];
                    v.y = acc[mt][nt][i2*2+1];
                    *(float2*)(op + col) = v;
                }
            }
        }
    }
}

// ---------------- combine ----------------
__global__ void __launch_bounds__(256) combine_kernel(
    float* __restrict__ out, const float* __restrict__ shared_gate)
{
    const int idx = blockIdx.x * 256 + threadIdx.x;
    const float sig = 1.f / (1.f + expf(-shared_gate[0]));
    const int t = idx >> 10;
    const int h = idx & (H_DIM - 1);
    out[idx] = g_eout[(size_t)(2 * t) * H_DIM + h]
             + g_eout[(size_t)(2 * t + 1) * H_DIM + h]
             + g_shout[idx] * sig;
}

// ---------------- aux z-loss ----------------
__global__ void __launch_bounds__(256) aux_kernel(float* __restrict__ out)
{
    __shared__ float red[256];
    const int tid = threadIdx.x;
    float s = 0.f;
    for (int i = tid; i < T_TOK; i += 256) s += g_zsq[i];
    red[tid] = s;
    __syncthreads();
    for (int o = 128; o; o >>= 1) {
        if (tid < o) red[tid] += red[tid + o];
        __syncthreads();
    }
    if (tid == 0) out[(size_t)T_TOK * H_DIM] = red[0] * (1e-4f / T_TOK);
}

// ---------------- launch ----------------
extern "C" void kernel_launch(void* const* d_in, const int* in_sizes, int n_in,
                              void* d_out, int out_size)
{
    const float* x      = (const float*)d_in[0];
    const float* ln_g   = (const float*)d_in[1];
    const float* ln_b   = (const float*)d_in[2];
    const float* gate_w = (const float*)d_in[3];
    const float* bias   = (const float*)d_in[4];
    const float* Wg     = (const float*)d_in[5];
    const float* Wu     = (const float*)d_in[6];
    const float* Wd     = (const float*)d_in[7];
    const float* sh_g   = (const float*)d_in[8];
    const float* sh_b   = (const float*)d_in[9];
    const float* sWg    = (const float*)d_in[10];
    const float* sWu    = (const float*)d_in[11];
    const float* sWd    = (const float*)d_in[12];
    const float* sgate  = (const float*)d_in[13];
    float* out = (float*)d_out;

    static int attr_done = 0;
    if (!attr_done) {
        cudaFuncSetAttribute(gemm_gateup,
            cudaFuncAttributeMaxDynamicSharedMemorySize, NSTAGE * GU_STAGE);
        cudaFuncSetAttribute(gemm_down,
            cudaFuncAttributeMaxDynamicSharedMemorySize, NSTAGE * DN_STAGE);
        attr_done = 1;
    }

    // device pointers to globals (device-side symbols usable directly in kernels;
    // here we need them as arguments -> use cudaGetSymbolAddress-free approach:
    // kernels reference globals directly; converts write via symbol pointers)
    __half* xh;  cudaGetSymbolAddress((void**)&xh,  g_xh);
    __half* xsh; cudaGetSymbolAddress((void**)&xsh, g_xsh);
    __half* hWg; cudaGetSymbolAddress((void**)&hWg, g_hWg);
    __half* hWu; cudaGetSymbolAddress((void**)&hWu, g_hWu);
    __half* hWd; cudaGetSymbolAddress((void**)&hWd, g_hWd);
    __half* hsWg; cudaGetSymbolAddress((void**)&hsWg, g_hsWg);
    __half* hsWu; cudaGetSymbolAddress((void**)&hsWu, g_hsWu);
    __half* hsWd; cudaGetSymbolAddress((void**)&hsWd, g_hsWd);

    zero_cnt_kernel<<<1, 32>>>();
    router_kernel<<<T_TOK, 256>>>(x, ln_g, ln_b, gate_w, bias, sh_g, sh_b);

    // fp32 -> fp16 conversions
    const int NW = N_EXP * I_DIM * H_DIM;       // 16.8M
    const int NS = I_DIM * H_DIM;               // 2.1M
    const int NX = T_TOK * H_DIM;               // 4.2M
    cvt_f2h<<<(NX/8 + 255)/256, 256>>>(x,   xh,  NX/8);
    cvt_f2h<<<(NW/8 + 255)/256, 256>>>(Wg,  hWg, NW/8);
    cvt_f2h<<<(NW/8 + 255)/256, 256>>>(Wu,  hWu, NW/8);
    cvt_f2h<<<(NW/8 + 255)/256, 256>>>(Wd,  hWd, NW/8);
    cvt_f2h<<<(NS/8 + 255)/256, 256>>>(sWg, hsWg, NS/8);
    cvt_f2h<<<(NS/8 + 255)/256, 256>>>(sWu, hsWu, NS/8);
    cvt_f2h<<<(NS/8 + 255)/256, 256>>>(sWd, hsWd, NS/8);

    dim3 gu_grid(T_TOK / BM, I_DIM / BN, N_EXP);
    gemm_gateup<<<gu_grid, 256, NSTAGE * GU_STAGE>>>(xh, hWg, hWu, 1);
    dim3 gus_grid(T_TOK / BM, I_DIM / BN, 1);
    gemm_gateup<<<gus_grid, 256, NSTAGE * GU_STAGE>>>(xsh, hsWg, hsWu, 0);

    dim3 dn_grid(T_TOK / BM, H_DIM / BN, N_EXP);
    gemm_down<<<dn_grid, 256, NSTAGE * DN_STAGE>>>(hWd, 1);
    dim3 dns_grid(T_TOK / BM, H_DIM / BN, 1);
    gemm_down<<<dns_grid, 256, NSTAGE * DN_STAGE>>>(hsWd, 0);

    combine_kernel<<<(T_TOK * H_DIM) / 256, 256>>>(out, sgate);
    aux_kernel<<<1, 256>>>(out);
}

// round 7
// speedup vs baseline: 4.3404x; 1.0868x over previous
#include <cuda_runtime.h>
#include <cuda_fp16.h>
#include <stdint.h>
#include <math.h>

// Problem constants
#define T_TOK 4096
#define H_DIM 1024
#define I_DIM 2048
#define N_EXP 8

// ---------------- scratch (static device globals; no allocs) ----------------
__device__ int    g_cnt[N_EXP];
__device__ int    g_tok[N_EXP][T_TOK];
__device__ float  g_wt [N_EXP][T_TOK];
__device__ int    g_slot[N_EXP][T_TOK];                  // output slot = 2*t + rank
__device__ __half g_hidden[(size_t)2 * T_TOK * I_DIM];   // routed SwiGLU hidden
__device__ float  g_eout [(size_t)2 * T_TOK * H_DIM];    // routed expert out
__device__ __half g_shid [(size_t)T_TOK * I_DIM];        // shared hidden
__device__ float  g_shout[(size_t)T_TOK * H_DIM];        // shared out
__device__ float  g_zsq[T_TOK];

// fp16 copies (pre-converted once per launch)
__device__ __half g_xh  [(size_t)T_TOK * H_DIM];
__device__ __half g_xsh [(size_t)T_TOK * H_DIM];
__device__ __half g_hWg [(size_t)N_EXP * I_DIM * H_DIM];
__device__ __half g_hWu [(size_t)N_EXP * I_DIM * H_DIM];
__device__ __half g_hWd [(size_t)N_EXP * H_DIM * I_DIM];
__device__ __half g_hsWg[(size_t)I_DIM * H_DIM];
__device__ __half g_hsWu[(size_t)I_DIM * H_DIM];
__device__ __half g_hsWd[(size_t)H_DIM * I_DIM];

__device__ __forceinline__ uint32_t h2u(half2 h) { return *(uint32_t*)&h; }
__device__ __forceinline__ uint32_t smem_u32(const void* p) {
    return (uint32_t)__cvta_generic_to_shared(p);
}
__device__ __forceinline__ uint4 cvt8(float4 a, float4 b) {
    uint4 r;
    r.x = h2u(__floats2half2_rn(a.x, a.y));
    r.y = h2u(__floats2half2_rn(a.z, a.w));
    r.z = h2u(__floats2half2_rn(b.x, b.y));
    r.w = h2u(__floats2half2_rn(b.z, b.w));
    return r;
}

// ---------------- fp32 -> fp16 convert (8 elems/thread) ----------------
__global__ void __launch_bounds__(256) cvt_f2h(
    const float* __restrict__ src, __half* __restrict__ dst, int n8)
{
    int i = blockIdx.x * 256 + threadIdx.x;
    if (i >= n8) return;
    float4 a = ((const float4*)src)[2 * i];
    float4 b = ((const float4*)src)[2 * i + 1];
    ((uint4*)dst)[i] = cvt8(a, b);
}

// ---------------- zero counters ----------------
__global__ void zero_cnt_kernel() {
    if (threadIdx.x < N_EXP) g_cnt[threadIdx.x] = 0;
}

// ---------------- router ----------------
__global__ void __launch_bounds__(256) router_kernel(
    const float* __restrict__ x,
    const float* __restrict__ ln_g, const float* __restrict__ ln_b,
    const float* __restrict__ gate_w, const float* __restrict__ bias,
    const float* __restrict__ sh_g, const float* __restrict__ sh_b)
{
    __shared__ float sx[H_DIM];
    __shared__ float sred[8], sred2[8];
    __shared__ float s_mean, s_rstd;
    __shared__ float logits[N_EXP];

    const int t   = blockIdx.x;
    const int tid = threadIdx.x;
    const float* xr = x + (size_t)t * H_DIM;

    float s = 0.f, s2 = 0.f;
#pragma unroll
    for (int i = 0; i < H_DIM / 256; i++) {
        float v = xr[tid + i * 256];
        sx[tid + i * 256] = v;
        s += v; s2 += v * v;
    }
#pragma unroll
    for (int o = 16; o; o >>= 1) {
        s  += __shfl_xor_sync(0xffffffffu, s,  o);
        s2 += __shfl_xor_sync(0xffffffffu, s2, o);
    }
    const int wid = tid >> 5, lane = tid & 31;
    if (lane == 0) { sred[wid] = s; sred2[wid] = s2; }
    __syncthreads();
    if (tid == 0) {
        float a = 0.f, b = 0.f;
        for (int i = 0; i < 8; i++) { a += sred[i]; b += sred2[i]; }
        float mean = a * (1.f / H_DIM);
        float var  = b * (1.f / H_DIM) - mean * mean;
        s_mean = mean;
        s_rstd = rsqrtf(var + 1e-5f);
    }
    __syncthreads();
    const float mean = s_mean, rstd = s_rstd;

    {
        const float* gw = gate_w + wid * H_DIM;
        float acc = 0.f;
        for (int i = lane; i < H_DIM; i += 32) {
            float hn = (sx[i] - mean) * rstd * ln_g[i] + ln_b[i];
            acc += hn * gw[i];
        }
#pragma unroll
        for (int o = 16; o; o >>= 1) acc += __shfl_xor_sync(0xffffffffu, acc, o);
        if (lane == 0) logits[wid] = acc + bias[wid];
    }

    // shared-expert LN -> half
#pragma unroll
    for (int i = 0; i < H_DIM / 256; i++) {
        int idx = tid + i * 256;
        float v = (sx[idx] - mean) * rstd * sh_g[idx] + sh_b[idx];
        g_xsh[(size_t)t * H_DIM + idx] = __float2half_rn(v);
    }
    __syncthreads();

    if (tid == 0) {
        float mx = logits[0];
#pragma unroll
        for (int e = 1; e < N_EXP; e++) mx = fmaxf(mx, logits[e]);
        float p[N_EXP]; float se = 0.f;
#pragma unroll
        for (int e = 0; e < N_EXP; e++) { p[e] = expf(logits[e] - mx); se += p[e]; }
        float z = mx + logf(se);
        g_zsq[t] = z * z;
        int e1 = 0;
#pragma unroll
        for (int e = 1; e < N_EXP; e++) if (p[e] > p[e1]) e1 = e;
        int e2 = (e1 == 0) ? 1 : 0;
#pragma unroll
        for (int e = 0; e < N_EXP; e++) if (e != e1 && p[e] > p[e2]) e2 = e;
        float inv = 1.f / se;
        float p1 = p[e1] * inv, p2 = p[e2] * inv;
        float sm = fmaxf(p1 + p2, 1e-5f);
        int pos = atomicAdd(&g_cnt[e1], 1);
        g_tok[e1][pos] = t; g_wt[e1][pos] = p1 / sm; g_slot[e1][pos] = 2 * t;
        pos = atomicAdd(&g_cnt[e2], 1);
        g_tok[e2][pos] = t; g_wt[e2][pos] = p2 / sm; g_slot[e2][pos] = 2 * t + 1;
    }
}

// ================= HMMA GEMMs: 128x128 block, 4 warps of 64x64 =================
#define BM 128
#define BK 32
#define NSTAGE 4
#define TILE_PITCH 80                 // bytes per row (32 halves data + 16B pad)
#define TILE_BYTES (128 * TILE_PITCH) // 10240
#define B_OFF TILE_BYTES
#define STAGE_BYTES (2 * TILE_BYTES)  // 20480
#define SMEM_DYN (NSTAGE * STAGE_BYTES + 1024)

#define MMA16816(d, a, b) \
  asm volatile("mma.sync.aligned.m16n8k16.row.col.f32.f16.f16.f32 " \
    "{%0,%1,%2,%3}, {%4,%5,%6,%7}, {%8,%9}, {%0,%1,%2,%3};" \
    : "+f"((d)[0]), "+f"((d)[1]), "+f"((d)[2]), "+f"((d)[3]) \
    : "r"((a)[0]), "r"((a)[1]), "r"((a)[2]), "r"((a)[3]), "r"((b)[0]), "r"((b)[1]))

#define LDSM4(r0, r1, r2, r3, addr) \
  asm volatile("ldmatrix.sync.aligned.m8n8.x4.shared.b16 {%0,%1,%2,%3}, [%4];" \
    : "=r"(r0), "=r"(r1), "=r"(r2), "=r"(r3) : "r"(addr))

#define CPA16(dst, src, sz) \
  asm volatile("cp.async.cg.shared.global [%0], [%1], 16, %2;" \
    :: "r"(dst), "l"(src), "r"(sz))
#define CPCOMMIT() asm volatile("cp.async.commit_group;")
#define CPWAIT(n)  asm volatile("cp.async.wait_group %0;" :: "n"(n))

// fused gate/up GEMM + SwiGLU.  z: 0..7 routed, 8 = shared.
// B tile rows: [0:32)=Wg n0+0..31, [32:64)=Wu n0+0..31,
//              [64:96)=Wg n0+32..63, [96:128)=Wu n0+32..63.
__global__ void __launch_bounds__(128) hm_gateup(
    const __half* __restrict__ xh,  const __half* __restrict__ xsh,
    const __half* __restrict__ Wg_all, const __half* __restrict__ Wu_all,
    const __half* __restrict__ sWg, const __half* __restrict__ sWu)
{
    extern __shared__ uint8_t dsm[];
    const int e = blockIdx.z;
    const bool se = (e == N_EXP);
    const int cnt = se ? T_TOK : g_cnt[e];
    const int m0 = blockIdx.x * BM;
    if (m0 >= cnt) return;
    const int n0 = blockIdx.y * 64;           // 64 intermediate cols per block

    const __half* xp = se ? xsh : xh;
    const __half* wg = se ? sWg : Wg_all + (size_t)e * I_DIM * H_DIM;
    const __half* wu = se ? sWu : Wu_all + (size_t)e * I_DIM * H_DIM;
    __half* hid = se ? g_shid : g_hidden;

    const int tid  = threadIdx.x;
    const int lane = tid & 31;
    const int wid  = tid >> 5;
    const int wm   = (wid & 1) * 64;
    const int wn   = (wid >> 1) * 64;
    const int fr   = lane >> 2;
    const int fc   = lane & 3;

    // loaders: thread tid -> A row tid, B row tid
    const __half* aptr = xp;
    uint32_t asz = 0;
    if (m0 + tid < cnt) {
        int r = se ? (m0 + tid) : g_tok[e][m0 + tid];
        aptr = xp + (size_t)r * H_DIM;
        asz = 16u;
    }
    const __half* bbase = (tid & 32) ? wu : wg;
    const __half* bptr = bbase + (size_t)(n0 + ((tid >> 6) << 5) + (tid & 31)) * H_DIM;

    const uint32_t sb = (smem_u32(dsm) + 1023) & ~1023u;
    const uint32_t adst = sb + tid * TILE_PITCH;
    const uint32_t bdst = sb + B_OFF + tid * TILE_PITCH;
    const uint32_t loff = (uint32_t)(((lane & 7) + ((lane >> 3) & 1) * 8) * TILE_PITCH
                                     + ((lane >> 4) & 1) * 16);

    float acc[4][8][4] = {};
    const int NCH = H_DIM / BK;   // 32

#define GU_ISSUE(c) do { \
    uint32_t st_ = (uint32_t)((c) & (NSTAGE - 1)) * STAGE_BYTES; \
    const __half* a_ = aptr + (c) * BK; \
    const __half* b_ = bptr + (c) * BK; \
    _Pragma("unroll") \
    for (int sg = 0; sg < 4; sg++) { \
        CPA16(adst + st_ + sg * 16, a_ + sg * 8, asz); \
        CPA16(bdst + st_ + sg * 16, b_ + sg * 8, 16u); \
    } \
} while (0)

#pragma unroll
    for (int s = 0; s < NSTAGE - 1; s++) { GU_ISSUE(s); CPCOMMIT(); }

    for (int c = 0; c < NCH; c++) {
        CPWAIT(NSTAGE - 2);
        __syncthreads();
        if (c + NSTAGE - 1 < NCH) GU_ISSUE(c + NSTAGE - 1);
        CPCOMMIT();
        const uint32_t st = (uint32_t)(c & (NSTAGE - 1)) * STAGE_BYTES;
        const uint32_t Ab = sb + st + loff;
        const uint32_t Bb = sb + st + B_OFF + loff;
#pragma unroll
        for (int s = 0; s < 2; s++) {
            uint32_t a[4][4];
#pragma unroll
            for (int mt = 0; mt < 4; mt++)
                LDSM4(a[mt][0], a[mt][1], a[mt][2], a[mt][3],
                      Ab + (wm + mt * 16) * TILE_PITCH + s * 32);
            uint32_t b[8][2];
#pragma unroll
            for (int np = 0; np < 4; np++) {
                uint32_t q0, q1, q2, q3;
                LDSM4(q0, q1, q2, q3, Bb + (wn + np * 16) * TILE_PITCH + s * 32);
                b[2*np][0] = q0; b[2*np][1] = q2;
                b[2*np+1][0] = q1; b[2*np+1][1] = q3;
            }
#pragma unroll
            for (int mt = 0; mt < 4; mt++)
#pragma unroll
                for (int nt = 0; nt < 8; nt++)
                    MMA16816(acc[mt][nt], a[mt], b[nt]);
        }
    }

    // epilogue: silu(gate)*up.  Within warp: nt 0..3 = gate cols, nt 4..7 = up cols.
    const int colbase = n0 + (wn >> 1);   // wn in {0,64} -> +0 / +32
#pragma unroll
    for (int mt = 0; mt < 4; mt++) {
#pragma unroll
        for (int i2 = 0; i2 < 2; i2++) {
            int row = wm + mt * 16 + fr + i2 * 8;
            int m = m0 + row;
            if (m >= cnt) continue;
            int orow = se ? m : g_slot[e][m];
            __half* op = hid + (size_t)orow * I_DIM + colbase;
#pragma unroll
            for (int j = 0; j < 4; j++) {
                float g0 = acc[mt][j][i2*2+0],   g1 = acc[mt][j][i2*2+1];
                float u0 = acc[mt][4+j][i2*2+0], u1 = acc[mt][4+j][i2*2+1];
                float v0 = (g0 / (1.f + expf(-g0))) * u0;
                float v1 = (g1 / (1.f + expf(-g1))) * u1;
                *(half2*)(op + j * 8 + 2 * fc) = __floats2half2_rn(v0, v1);
            }
        }
    }
}

// down GEMM (+ combine weight for routed). 128 H-cols per block.
__global__ void __launch_bounds__(128) hm_down(
    const __half* __restrict__ Wd_all, const __half* __restrict__ sWd)
{
    extern __shared__ uint8_t dsm[];
    const int e = blockIdx.z;
    const bool se = (e == N_EXP);
    const int cnt = se ? T_TOK : g_cnt[e];
    const int m0 = blockIdx.x * BM;
    if (m0 >= cnt) return;
    const int n0 = blockIdx.y * 128;

    const __half* hid = se ? g_shid : g_hidden;
    const __half* wd  = se ? sWd : Wd_all + (size_t)e * H_DIM * I_DIM;

    const int tid  = threadIdx.x;
    const int lane = tid & 31;
    const int wid  = tid >> 5;
    const int wm   = (wid & 1) * 64;
    const int wn   = (wid >> 1) * 64;
    const int fr   = lane >> 2;
    const int fc   = lane & 3;

    const __half* aptr = hid;
    uint32_t asz = 0;
    if (m0 + tid < cnt) {
        int slot = se ? (m0 + tid) : g_slot[e][m0 + tid];
        aptr = hid + (size_t)slot * I_DIM;
        asz = 16u;
    }
    const __half* bptr = wd + (size_t)(n0 + tid) * I_DIM;

    const uint32_t sb = (smem_u32(dsm) + 1023) & ~1023u;
    const uint32_t adst = sb + tid * TILE_PITCH;
    const uint32_t bdst = sb + B_OFF + tid * TILE_PITCH;
    const uint32_t loff = (uint32_t)(((lane & 7) + ((lane >> 3) & 1) * 8) * TILE_PITCH
                                     + ((lane >> 4) & 1) * 16);

    float acc[4][8][4] = {};
    const int NCH = I_DIM / BK;   // 64

#define DN_ISSUE(c) do { \
    uint32_t st_ = (uint32_t)((c) & (NSTAGE - 1)) * STAGE_BYTES; \
    const __half* a_ = aptr + (c) * BK; \
    const __half* b_ = bptr + (c) * BK; \
    _Pragma("unroll") \
    for (int sg = 0; sg < 4; sg++) { \
        CPA16(adst + st_ + sg * 16, a_ + sg * 8, asz); \
        CPA16(bdst + st_ + sg * 16, b_ + sg * 8, 16u); \
    } \
} while (0)

#pragma unroll
    for (int s = 0; s < NSTAGE - 1; s++) { DN_ISSUE(s); CPCOMMIT(); }

    for (int c = 0; c < NCH; c++) {
        CPWAIT(NSTAGE - 2);
        __syncthreads();
        if (c + NSTAGE - 1 < NCH) DN_ISSUE(c + NSTAGE - 1);
        CPCOMMIT();
        const uint32_t st = (uint32_t)(c & (NSTAGE - 1)) * STAGE_BYTES;
        const uint32_t Ab = sb + st + loff;
        const uint32_t Bb = sb + st + B_OFF + loff;
#pragma unroll
        for (int s = 0; s < 2; s++) {
            uint32_t a[4][4];
#pragma unroll
            for (int mt = 0; mt < 4; mt++)
                LDSM4(a[mt][0], a[mt][1], a[mt][2], a[mt][3],
                      Ab + (wm + mt * 16) * TILE_PITCH + s * 32);
            uint32_t b[8][2];
#pragma unroll
            for (int np = 0; np < 4; np++) {
                uint32_t q0, q1, q2, q3;
                LDSM4(q0, q1, q2, q3, Bb + (wn + np * 16) * TILE_PITCH + s * 32);
                b[2*np][0] = q0; b[2*np][1] = q2;
                b[2*np+1][0] = q1; b[2*np+1][1] = q3;
            }
#pragma unroll
            for (int mt = 0; mt < 4; mt++)
#pragma unroll
                for (int nt = 0; nt < 8; nt++)
                    MMA16816(acc[mt][nt], a[mt], b[nt]);
        }
    }

#pragma unroll
    for (int mt = 0; mt < 4; mt++) {
#pragma unroll
        for (int i2 = 0; i2 < 2; i2++) {
            int row = wm + mt * 16 + fr + i2 * 8;
            int m = m0 + row;
            if (m >= cnt) continue;
            if (se) {
                float* op = g_shout + (size_t)m * H_DIM + n0 + wn;
#pragma unroll
                for (int nt = 0; nt < 8; nt++) {
                    float2 v;
                    v.x = acc[mt][nt][i2*2+0];
                    v.y = acc[mt][nt][i2*2+1];
                    *(float2*)(op + nt * 8 + 2 * fc) = v;
                }
            } else {
                int orow = g_slot[e][m];
                float w  = g_wt[e][m];
                float* op = g_eout + (size_t)orow * H_DIM + n0 + wn;
#pragma unroll
                for (int nt = 0; nt < 8; nt++) {
                    float2 v;
                    v.x = acc[mt][nt][i2*2+0] * w;
                    v.y = acc[mt][nt][i2*2+1] * w;
                    *(float2*)(op + nt * 8 + 2 * fc) = v;
                }
            }
        }
    }
}

// ---------------- combine ----------------
__global__ void __launch_bounds__(256) combine_kernel(
    float* __restrict__ out, const float* __restrict__ shared_gate)
{
    const int idx = blockIdx.x * 256 + threadIdx.x;
    const float sig = 1.f / (1.f + expf(-shared_gate[0]));
    const int t = idx >> 10;
    const int h = idx & (H_DIM - 1);
    out[idx] = g_eout[(size_t)(2 * t) * H_DIM + h]
             + g_eout[(size_t)(2 * t + 1) * H_DIM + h]
             + g_shout[idx] * sig;
}

// ---------------- aux z-loss ----------------
__global__ void __launch_bounds__(256) aux_kernel(float* __restrict__ out)
{
    __shared__ float red[256];
    const int tid = threadIdx.x;
    float s = 0.f;
    for (int i = tid; i < T_TOK; i += 256) s += g_zsq[i];
    red[tid] = s;
    __syncthreads();
    for (int o = 128; o; o >>= 1) {
        if (tid < o) red[tid] += red[tid + o];
        __syncthreads();
    }
    if (tid == 0) out[(size_t)T_TOK * H_DIM] = red[0] * (1e-4f / T_TOK);
}

// ---------------- launch ----------------
extern "C" void kernel_launch(void* const* d_in, const int* in_sizes, int n_in,
                              void* d_out, int out_size)
{
    const float* x      = (const float*)d_in[0];
    const float* ln_g   = (const float*)d_in[1];
    const float* ln_b   = (const float*)d_in[2];
    const float* gate_w = (const float*)d_in[3];
    const float* bias   = (const float*)d_in[4];
    const float* Wg     = (const float*)d_in[5];
    const float* Wu     = (const float*)d_in[6];
    const float* Wd     = (const float*)d_in[7];
    const float* sh_g   = (const float*)d_in[8];
    const float* sh_b   = (const float*)d_in[9];
    const float* sWg    = (const float*)d_in[10];
    const float* sWu    = (const float*)d_in[11];
    const float* sWd    = (const float*)d_in[12];
    const float* sgate  = (const float*)d_in[13];
    float* out = (float*)d_out;

    static int attr_done = 0;
    if (!attr_done) {
        cudaFuncSetAttribute(hm_gateup,
            cudaFuncAttributeMaxDynamicSharedMemorySize, SMEM_DYN);
        cudaFuncSetAttribute(hm_down,
            cudaFuncAttributeMaxDynamicSharedMemorySize, SMEM_DYN);
        attr_done = 1;
    }

    __half *xh, *xsh, *hWg, *hWu, *hWd, *hsWg, *hsWu, *hsWd;
    cudaGetSymbolAddress((void**)&xh,  g_xh);
    cudaGetSymbolAddress((void**)&xsh, g_xsh);
    cudaGetSymbolAddress((void**)&hWg, g_hWg);
    cudaGetSymbolAddress((void**)&hWu, g_hWu);
    cudaGetSymbolAddress((void**)&hWd, g_hWd);
    cudaGetSymbolAddress((void**)&hsWg, g_hsWg);
    cudaGetSymbolAddress((void**)&hsWu, g_hsWu);
    cudaGetSymbolAddress((void**)&hsWd, g_hsWd);

    zero_cnt_kernel<<<1, 32>>>();
    router_kernel<<<T_TOK, 256>>>(x, ln_g, ln_b, gate_w, bias, sh_g, sh_b);

    const int NW = N_EXP * I_DIM * H_DIM;
    const int NS = I_DIM * H_DIM;
    const int NX = T_TOK * H_DIM;
    cvt_f2h<<<(NX/8 + 255)/256, 256>>>(x,   xh,  NX/8);
    cvt_f2h<<<(NW/8 + 255)/256, 256>>>(Wg,  hWg, NW/8);
    cvt_f2h<<<(NW/8 + 255)/256, 256>>>(Wu,  hWu, NW/8);
    cvt_f2h<<<(NW/8 + 255)/256, 256>>>(Wd,  hWd, NW/8);
    cvt_f2h<<<(NS/8 + 255)/256, 256>>>(sWg, hsWg, NS/8);
    cvt_f2h<<<(NS/8 + 255)/256, 256>>>(sWu, hsWu, NS/8);
    cvt_f2h<<<(NS/8 + 255)/256, 256>>>(sWd, hsWd, NS/8);

    dim3 gu_grid(T_TOK / BM, I_DIM / 64, N_EXP + 1);
    hm_gateup<<<gu_grid, 128, SMEM_DYN>>>(xh, xsh, hWg, hWu, hsWg, hsWu);

    dim3 dn_grid(T_TOK / BM, H_DIM / 128, N_EXP + 1);
    hm_down<<<dn_grid, 128, SMEM_DYN>>>(hWd, hsWd);

    combine_kernel<<<(T_TOK * H_DIM) / 256, 256>>>(out, sgate);
    aux_kernel<<<1, 256>>>(out);
}

// round 8
// speedup vs baseline: 4.7969x; 1.1052x over previous
#include <cuda_runtime.h>
#include <cuda_fp16.h>
#include <stdint.h>
#include <math.h>

// Problem constants
#define T_TOK 4096
#define H_DIM 1024
#define I_DIM 2048
#define N_EXP 8

// ---------------- scratch (static device globals; no allocs) ----------------
__device__ int    g_cnt[N_EXP];
__device__ int    g_tok[N_EXP][T_TOK];
__device__ float  g_wt [N_EXP][T_TOK];
__device__ int    g_slot[N_EXP][T_TOK];                  // output slot = 2*t + rank
__device__ __half g_hidden[(size_t)2 * T_TOK * I_DIM];   // routed SwiGLU hidden
__device__ float  g_eout [(size_t)2 * T_TOK * H_DIM];    // routed expert out
__device__ __half g_shid [(size_t)T_TOK * I_DIM];        // shared hidden
__device__ float  g_shout[(size_t)T_TOK * H_DIM];        // shared out
__device__ float  g_zsq[T_TOK];

// fp16 copies (pre-converted once per launch)
__device__ __half g_xh  [(size_t)T_TOK * H_DIM];
__device__ __half g_xsh [(size_t)T_TOK * H_DIM];
__device__ __half g_hWg [(size_t)N_EXP * I_DIM * H_DIM];
__device__ __half g_hWu [(size_t)N_EXP * I_DIM * H_DIM];
__device__ __half g_hWd [(size_t)N_EXP * H_DIM * I_DIM];
__device__ __half g_hsWg[(size_t)I_DIM * H_DIM];
__device__ __half g_hsWu[(size_t)I_DIM * H_DIM];
__device__ __half g_hsWd[(size_t)H_DIM * I_DIM];

__device__ __forceinline__ uint32_t h2u(half2 h) { return *(uint32_t*)&h; }
__device__ __forceinline__ uint32_t smem_u32(const void* p) {
    return (uint32_t)__cvta_generic_to_shared(p);
}
__device__ __forceinline__ uint4 cvt8(float4 a, float4 b) {
    uint4 r;
    r.x = h2u(__floats2half2_rn(a.x, a.y));
    r.y = h2u(__floats2half2_rn(a.z, a.w));
    r.z = h2u(__floats2half2_rn(b.x, b.y));
    r.w = h2u(__floats2half2_rn(b.z, b.w));
    return r;
}

// ---------------- fused fp32 -> fp16 convert of all operands ----------------
// segment sizes in 8-elem groups (compile-time)
#define GX  (T_TOK * H_DIM / 8)              // 524288
#define GW  (N_EXP * I_DIM * H_DIM / 8)      // 2097152
#define GS  (I_DIM * H_DIM / 8)              // 262144
#define G_TOTAL (GX + 3 * GW + 3 * GS)       // 7602176

__global__ void __launch_bounds__(256) cvt_all(
    const float* __restrict__ x,
    const float* __restrict__ Wg, const float* __restrict__ Wu,
    const float* __restrict__ Wd,
    const float* __restrict__ sWg, const float* __restrict__ sWu,
    const float* __restrict__ sWd)
{
    unsigned i = blockIdx.x * 256 + threadIdx.x;
    if (i >= G_TOTAL) return;
    const float* s; __half* d; unsigned off;
    if (i < GX)                    { s = x;   d = g_xh;   off = i; }
    else if (i < GX + GW)          { s = Wg;  d = g_hWg;  off = i - GX; }
    else if (i < GX + 2*GW)        { s = Wu;  d = g_hWu;  off = i - GX - GW; }
    else if (i < GX + 3*GW)        { s = Wd;  d = g_hWd;  off = i - GX - 2*GW; }
    else if (i < GX + 3*GW + GS)   { s = sWg; d = g_hsWg; off = i - GX - 3*GW; }
    else if (i < GX + 3*GW + 2*GS) { s = sWu; d = g_hsWu; off = i - GX - 3*GW - GS; }
    else                           { s = sWd; d = g_hsWd; off = i - GX - 3*GW - 2*GS; }
    float4 a = ((const float4*)s)[2 * (size_t)off];
    float4 b = ((const float4*)s)[2 * (size_t)off + 1];
    ((uint4*)d)[off] = cvt8(a, b);
}

// ---------------- zero counters / profiling pad ----------------
__global__ void zero_cnt_kernel() {
    if (threadIdx.x < N_EXP) g_cnt[threadIdx.x] = 0;
}
__global__ void nop_kernel() {}

// ---------------- router ----------------
__global__ void __launch_bounds__(256) router_kernel(
    const float* __restrict__ x,
    const float* __restrict__ ln_g, const float* __restrict__ ln_b,
    const float* __restrict__ gate_w, const float* __restrict__ bias,
    const float* __restrict__ sh_g, const float* __restrict__ sh_b)
{
    __shared__ float sx[H_DIM];
    __shared__ float sred[8], sred2[8];
    __shared__ float s_mean, s_rstd;
    __shared__ float logits[N_EXP];

    const int t   = blockIdx.x;
    const int tid = threadIdx.x;
    const float* xr = x + (size_t)t * H_DIM;

    float s = 0.f, s2 = 0.f;
#pragma unroll
    for (int i = 0; i < H_DIM / 256; i++) {
        float v = xr[tid + i * 256];
        sx[tid + i * 256] = v;
        s += v; s2 += v * v;
    }
#pragma unroll
    for (int o = 16; o; o >>= 1) {
        s  += __shfl_xor_sync(0xffffffffu, s,  o);
        s2 += __shfl_xor_sync(0xffffffffu, s2, o);
    }
    const int wid = tid >> 5, lane = tid & 31;
    if (lane == 0) { sred[wid] = s; sred2[wid] = s2; }
    __syncthreads();
    if (tid == 0) {
        float a = 0.f, b = 0.f;
        for (int i = 0; i < 8; i++) { a += sred[i]; b += sred2[i]; }
        float mean = a * (1.f / H_DIM);
        float var  = b * (1.f / H_DIM) - mean * mean;
        s_mean = mean;
        s_rstd = rsqrtf(var + 1e-5f);
    }
    __syncthreads();
    const float mean = s_mean, rstd = s_rstd;

    {
        const float* gw = gate_w + wid * H_DIM;
        float acc = 0.f;
        for (int i = lane; i < H_DIM; i += 32) {
            float hn = (sx[i] - mean) * rstd * ln_g[i] + ln_b[i];
            acc += hn * gw[i];
        }
#pragma unroll
        for (int o = 16; o; o >>= 1) acc += __shfl_xor_sync(0xffffffffu, acc, o);
        if (lane == 0) logits[wid] = acc + bias[wid];
    }

    // shared-expert LN -> half
#pragma unroll
    for (int i = 0; i < H_DIM / 256; i++) {
        int idx = tid + i * 256;
        float v = (sx[idx] - mean) * rstd * sh_g[idx] + sh_b[idx];
        g_xsh[(size_t)t * H_DIM + idx] = __float2half_rn(v);
    }
    __syncthreads();

    if (tid == 0) {
        float mx = logits[0];
#pragma unroll
        for (int e = 1; e < N_EXP; e++) mx = fmaxf(mx, logits[e]);
        float p[N_EXP]; float se = 0.f;
#pragma unroll
        for (int e = 0; e < N_EXP; e++) { p[e] = expf(logits[e] - mx); se += p[e]; }
        float z = mx + logf(se);
        g_zsq[t] = z * z;
        int e1 = 0;
#pragma unroll
        for (int e = 1; e < N_EXP; e++) if (p[e] > p[e1]) e1 = e;
        int e2 = (e1 == 0) ? 1 : 0;
#pragma unroll
        for (int e = 0; e < N_EXP; e++) if (e != e1 && p[e] > p[e2]) e2 = e;
        float inv = 1.f / se;
        float p1 = p[e1] * inv, p2 = p[e2] * inv;
        float sm = fmaxf(p1 + p2, 1e-5f);
        int pos = atomicAdd(&g_cnt[e1], 1);
        g_tok[e1][pos] = t; g_wt[e1][pos] = p1 / sm; g_slot[e1][pos] = 2 * t;
        pos = atomicAdd(&g_cnt[e2], 1);
        g_tok[e2][pos] = t; g_wt[e2][pos] = p2 / sm; g_slot[e2][pos] = 2 * t + 1;
    }
}

// ===== HMMA GEMMs: 128x128 block, 8 warps of 32x64, 256 thr, 2 CTAs/SM =====
#define BM 128
#define BK 32
#define NSTAGE 4
#define TILE_PITCH 80
#define TILE_BYTES (128 * TILE_PITCH)
#define B_OFF TILE_BYTES
#define STAGE_BYTES (2 * TILE_BYTES)
#define SMEM_DYN (NSTAGE * STAGE_BYTES + 1024)

#define MMA16816(d, a, b) \
  asm volatile("mma.sync.aligned.m16n8k16.row.col.f32.f16.f16.f32 " \
    "{%0,%1,%2,%3}, {%4,%5,%6,%7}, {%8,%9}, {%0,%1,%2,%3};" \
    : "+f"((d)[0]), "+f"((d)[1]), "+f"((d)[2]), "+f"((d)[3]) \
    : "r"((a)[0]), "r"((a)[1]), "r"((a)[2]), "r"((a)[3]), "r"((b)[0]), "r"((b)[1]))

#define LDSM4(r0, r1, r2, r3, addr) \
  asm volatile("ldmatrix.sync.aligned.m8n8.x4.shared.b16 {%0,%1,%2,%3}, [%4];" \
    : "=r"(r0), "=r"(r1), "=r"(r2), "=r"(r3) : "r"(addr))

#define CPA16(dst, src, sz) \
  asm volatile("cp.async.cg.shared.global [%0], [%1], 16, %2;" \
    :: "r"(dst), "l"(src), "r"(sz))
#define CPCOMMIT() asm volatile("cp.async.commit_group;")
#define CPWAIT(n)  asm volatile("cp.async.wait_group %0;" :: "n"(n))

// fused gate/up GEMM + SwiGLU.  z: 0..7 routed, 8 = shared.
// B tile rows: [0:32)=Wg n0+0..31, [32:64)=Wu n0+0..31,
//              [64:96)=Wg n0+32..63, [96:128)=Wu n0+32..63.
__global__ void __launch_bounds__(256, 2) hm_gateup(
    const __half* __restrict__ xh,  const __half* __restrict__ xsh,
    const __half* __restrict__ Wg_all, const __half* __restrict__ Wu_all,
    const __half* __restrict__ sWg, const __half* __restrict__ sWu)
{
    extern __shared__ uint8_t dsm[];
    const int e = blockIdx.z;
    const bool se = (e == N_EXP);
    const int cnt = se ? T_TOK : g_cnt[e];
    const int m0 = blockIdx.x * BM;
    if (m0 >= cnt) return;
    const int n0 = blockIdx.y * 64;

    const __half* xp = se ? xsh : xh;
    const __half* wg = se ? sWg : Wg_all + (size_t)e * I_DIM * H_DIM;
    const __half* wu = se ? sWu : Wu_all + (size_t)e * I_DIM * H_DIM;
    __half* hid = se ? g_shid : g_hidden;

    const int tid  = threadIdx.x;
    const int lane = tid & 31;
    const int wid  = tid >> 5;
    const int wm   = (wid & 3) * 32;
    const int wn   = (wid >> 2) * 64;
    const int fr   = lane >> 2;
    const int fc   = lane & 3;

    // loaders: 256 threads; thread handles row tid&127, two 16B segs (tid>>7)*2+{0,1}
    const int arow = tid & 127;
    const int ah   = (tid >> 7) * 2;
    const __half* aptr = xp;
    uint32_t asz = 0;
    if (m0 + arow < cnt) {
        int r = se ? (m0 + arow) : g_tok[e][m0 + arow];
        aptr = xp + (size_t)r * H_DIM;
        asz = 16u;
    }
    const int brow = tid & 127;
    const __half* bbase = (brow & 32) ? wu : wg;
    const __half* bptr = bbase + (size_t)(n0 + ((brow >> 6) << 5) + (brow & 31)) * H_DIM;

    const uint32_t sb = (smem_u32(dsm) + 1023) & ~1023u;
    const uint32_t adst = sb + arow * TILE_PITCH + ah * 16;
    const uint32_t bdst = sb + B_OFF + brow * TILE_PITCH + ah * 16;
    const uint32_t loff = (uint32_t)(((lane & 7) + ((lane >> 3) & 1) * 8) * TILE_PITCH
                                     + ((lane >> 4) & 1) * 16);

    float acc[2][8][4] = {};
    const int NCH = H_DIM / BK;   // 32

#define GU_ISSUE(c) do { \
    uint32_t st_ = (uint32_t)((c) & (NSTAGE - 1)) * STAGE_BYTES; \
    const __half* a_ = aptr + (c) * BK + ah * 8; \
    const __half* b_ = bptr + (c) * BK + ah * 8; \
    CPA16(adst + st_,      a_,     asz); \
    CPA16(adst + st_ + 16, a_ + 8, asz); \
    CPA16(bdst + st_,      b_,     16u); \
    CPA16(bdst + st_ + 16, b_ + 8, 16u); \
} while (0)

#pragma unroll
    for (int s = 0; s < NSTAGE - 1; s++) { GU_ISSUE(s); CPCOMMIT(); }

    for (int c = 0; c < NCH; c++) {
        CPWAIT(NSTAGE - 2);
        __syncthreads();
        if (c + NSTAGE - 1 < NCH) GU_ISSUE(c + NSTAGE - 1);
        CPCOMMIT();
        const uint32_t st = (uint32_t)(c & (NSTAGE - 1)) * STAGE_BYTES;
        const uint32_t Ab = sb + st + loff;
        const uint32_t Bb = sb + st + B_OFF + loff;
#pragma unroll
        for (int s = 0; s < 2; s++) {
            uint32_t a[2][4];
#pragma unroll
            for (int mt = 0; mt < 2; mt++)
                LDSM4(a[mt][0], a[mt][1], a[mt][2], a[mt][3],
                      Ab + (wm + mt * 16) * TILE_PITCH + s * 32);
            uint32_t b[8][2];
#pragma unroll
            for (int np = 0; np < 4; np++) {
                uint32_t q0, q1, q2, q3;
                LDSM4(q0, q1, q2, q3, Bb + (wn + np * 16) * TILE_PITCH + s * 32);
                b[2*np][0] = q0; b[2*np][1] = q2;
                b[2*np+1][0] = q1; b[2*np+1][1] = q3;
            }
#pragma unroll
            for (int mt = 0; mt < 2; mt++)
#pragma unroll
                for (int nt = 0; nt < 8; nt++)
                    MMA16816(acc[mt][nt], a[mt], b[nt]);
        }
    }

    // epilogue: silu(gate)*up; nt 0..3 gate, 4..7 matching up
    const int colbase = n0 + (wn >> 1);   // wn in {0,64} -> +0/+32
#pragma unroll
    for (int mt = 0; mt < 2; mt++) {
#pragma unroll
        for (int i2 = 0; i2 < 2; i2++) {
            int row = wm + mt * 16 + fr + i2 * 8;
            int m = m0 + row;
            if (m >= cnt) continue;
            int orow = se ? m : g_slot[e][m];
            __half* op = hid + (size_t)orow * I_DIM + colbase;
#pragma unroll
            for (int j = 0; j < 4; j++) {
                float g0 = acc[mt][j][i2*2+0],   g1 = acc[mt][j][i2*2+1];
                float u0 = acc[mt][4+j][i2*2+0], u1 = acc[mt][4+j][i2*2+1];
                float v0 = (g0 / (1.f + expf(-g0))) * u0;
                float v1 = (g1 / (1.f + expf(-g1))) * u1;
                *(half2*)(op + j * 8 + 2 * fc) = __floats2half2_rn(v0, v1);
            }
        }
    }
}

// down GEMM (+ combine weight for routed). 128 H-cols per block.
__global__ void __launch_bounds__(256, 2) hm_down(
    const __half* __restrict__ Wd_all, const __half* __restrict__ sWd)
{
    extern __shared__ uint8_t dsm[];
    const int e = blockIdx.z;
    const bool se = (e == N_EXP);
    const int cnt = se ? T_TOK : g_cnt[e];
    const int m0 = blockIdx.x * BM;
    if (m0 >= cnt) return;
    const int n0 = blockIdx.y * 128;

    const __half* hid = se ? g_shid : g_hidden;
    const __half* wd  = se ? sWd : Wd_all + (size_t)e * H_DIM * I_DIM;

    const int tid  = threadIdx.x;
    const int lane = tid & 31;
    const int wid  = tid >> 5;
    const int wm   = (wid & 3) * 32;
    const int wn   = (wid >> 2) * 64;
    const int fr   = lane >> 2;
    const int fc   = lane & 3;

    const int arow = tid & 127;
    const int ah   = (tid >> 7) * 2;
    const __half* aptr = hid;
    uint32_t asz = 0;
    if (m0 + arow < cnt) {
        int slot = se ? (m0 + arow) : g_slot[e][m0 + arow];
        aptr = hid + (size_t)slot * I_DIM;
        asz = 16u;
    }
    const int brow = tid & 127;
    const __half* bptr = wd + (size_t)(n0 + brow) * I_DIM;

    const uint32_t sb = (smem_u32(dsm) + 1023) & ~1023u;
    const uint32_t adst = sb + arow * TILE_PITCH + ah * 16;
    const uint32_t bdst = sb + B_OFF + brow * TILE_PITCH + ah * 16;
    const uint32_t loff = (uint32_t)(((lane & 7) + ((lane >> 3) & 1) * 8) * TILE_PITCH
                                     + ((lane >> 4) & 1) * 16);

    float acc[2][8][4] = {};
    const int NCH = I_DIM / BK;   // 64

#define DN_ISSUE(c) do { \
    uint32_t st_ = (uint32_t)((c) & (NSTAGE - 1)) * STAGE_BYTES; \
    const __half* a_ = aptr + (c) * BK + ah * 8; \
    const __half* b_ = bptr + (c) * BK + ah * 8; \
    CPA16(adst + st_,      a_,     asz); \
    CPA16(adst + st_ + 16, a_ + 8, asz); \
    CPA16(bdst + st_,      b_,     16u); \
    CPA16(bdst + st_ + 16, b_ + 8, 16u); \
} while (0)

#pragma unroll
    for (int s = 0; s < NSTAGE - 1; s++) { DN_ISSUE(s); CPCOMMIT(); }

    for (int c = 0; c < NCH; c++) {
        CPWAIT(NSTAGE - 2);
        __syncthreads();
        if (c + NSTAGE - 1 < NCH) DN_ISSUE(c + NSTAGE - 1);
        CPCOMMIT();
        const uint32_t st = (uint32_t)(c & (NSTAGE - 1)) * STAGE_BYTES;
        const uint32_t Ab = sb + st + loff;
        const uint32_t Bb = sb + st + B_OFF + loff;
#pragma unroll
        for (int s = 0; s < 2; s++) {
            uint32_t a[2][4];
#pragma unroll
            for (int mt = 0; mt < 2; mt++)
                LDSM4(a[mt][0], a[mt][1], a[mt][2], a[mt][3],
                      Ab + (wm + mt * 16) * TILE_PITCH + s * 32);
            uint32_t b[8][2];
#pragma unroll
            for (int np = 0; np < 4; np++) {
                uint32_t q0, q1, q2, q3;
                LDSM4(q0, q1, q2, q3, Bb + (wn + np * 16) * TILE_PITCH + s * 32);
                b[2*np][0] = q0; b[2*np][1] = q2;
                b[2*np+1][0] = q1; b[2*np+1][1] = q3;
            }
#pragma unroll
            for (int mt = 0; mt < 2; mt++)
#pragma unroll
                for (int nt = 0; nt < 8; nt++)
                    MMA16816(acc[mt][nt], a[mt], b[nt]);
        }
    }

#pragma unroll
    for (int mt = 0; mt < 2; mt++) {
#pragma unroll
        for (int i2 = 0; i2 < 2; i2++) {
            int row = wm + mt * 16 + fr + i2 * 8;
            int m = m0 + row;
            if (m >= cnt) continue;
            if (se) {
                float* op = g_shout + (size_t)m * H_DIM + n0 + wn;
#pragma unroll
                for (int nt = 0; nt < 8; nt++) {
                    float2 v;
                    v.x = acc[mt][nt][i2*2+0];
                    v.y = acc[mt][nt][i2*2+1];
                    *(float2*)(op + nt * 8 + 2 * fc) = v;
                }
            } else {
                int orow = g_slot[e][m];
                float w  = g_wt[e][m];
                float* op = g_eout + (size_t)orow * H_DIM + n0 + wn;
#pragma unroll
                for (int nt = 0; nt < 8; nt++) {
                    float2 v;
                    v.x = acc[mt][nt][i2*2+0] * w;
                    v.y = acc[mt][nt][i2*2+1] * w;
                    *(float2*)(op + nt * 8 + 2 * fc) = v;
                }
            }
        }
    }
}

// ---------------- combine ----------------
__global__ void __launch_bounds__(256) combine_kernel(
    float* __restrict__ out, const float* __restrict__ shared_gate)
{
    const int idx = blockIdx.x * 256 + threadIdx.x;
    const float sig = 1.f / (1.f + expf(-shared_gate[0]));
    const int t = idx >> 10;
    const int h = idx & (H_DIM - 1);
    out[idx] = g_eout[(size_t)(2 * t) * H_DIM + h]
             + g_eout[(size_t)(2 * t + 1) * H_DIM + h]
             + g_shout[idx] * sig;
}

// ---------------- aux z-loss ----------------
__global__ void __launch_bounds__(256) aux_kernel(float* __restrict__ out)
{
    __shared__ float red[256];
    const int tid = threadIdx.x;
    float s = 0.f;
    for (int i = tid; i < T_TOK; i += 256) s += g_zsq[i];
    red[tid] = s;
    __syncthreads();
    for (int o = 128; o; o >>= 1) {
        if (tid < o) red[tid] += red[tid + o];
        __syncthreads();
    }
    if (tid == 0) out[(size_t)T_TOK * H_DIM] = red[0] * (1e-4f / T_TOK);
}

// ---------------- launch ----------------
extern "C" void kernel_launch(void* const* d_in, const int* in_sizes, int n_in,
                              void* d_out, int out_size)
{
    const float* x      = (const float*)d_in[0];
    const float* ln_g   = (const float*)d_in[1];
    const float* ln_b   = (const float*)d_in[2];
    const float* gate_w = (const float*)d_in[3];
    const float* bias   = (const float*)d_in[4];
    const float* Wg     = (const float*)d_in[5];
    const float* Wu     = (const float*)d_in[6];
    const float* Wd     = (const float*)d_in[7];
    const float* sh_g   = (const float*)d_in[8];
    const float* sh_b   = (const float*)d_in[9];
    const float* sWg    = (const float*)d_in[10];
    const float* sWu    = (const float*)d_in[11];
    const float* sWd    = (const float*)d_in[12];
    const float* sgate  = (const float*)d_in[13];
    float* out = (float*)d_out;

    static int attr_done = 0;
    if (!attr_done) {
        cudaFuncSetAttribute(hm_gateup,
            cudaFuncAttributeMaxDynamicSharedMemorySize, SMEM_DYN);
        cudaFuncSetAttribute(hm_down,
            cudaFuncAttributeMaxDynamicSharedMemorySize, SMEM_DYN);
        attr_done = 1;
    }

    __half *xh, *xsh;
    cudaGetSymbolAddress((void**)&xh,  g_xh);
    cudaGetSymbolAddress((void**)&xsh, g_xsh);
    __half *hWg, *hWu, *hWd, *hsWg, *hsWu, *hsWd;
    cudaGetSymbolAddress((void**)&hWg, g_hWg);
    cudaGetSymbolAddress((void**)&hWu, g_hWu);
    cudaGetSymbolAddress((void**)&hWd, g_hWd);
    cudaGetSymbolAddress((void**)&hsWg, g_hsWg);
    cudaGetSymbolAddress((void**)&hsWu, g_hsWu);
    cudaGetSymbolAddress((void**)&hsWd, g_hsWd);

    // launch order arranged so -s 5 -c 1 captures hm_gateup (launch #6)
    zero_cnt_kernel<<<1, 32>>>();                                      // 1
    router_kernel<<<T_TOK, 256>>>(x, ln_g, ln_b, gate_w, bias, sh_g, sh_b); // 2
    cvt_all<<<(G_TOTAL + 255) / 256, 256>>>(x, Wg, Wu, Wd, sWg, sWu, sWd);  // 3
    nop_kernel<<<1, 32>>>();                                           // 4
    nop_kernel<<<1, 32>>>();                                           // 5

    dim3 gu_grid(T_TOK / BM, I_DIM / 64, N_EXP + 1);
    hm_gateup<<<gu_grid, 256, SMEM_DYN>>>(xh, xsh, hWg, hWu, hsWg, hsWu);   // 6

    dim3 dn_grid(T_TOK / BM, H_DIM / 128, N_EXP + 1);
    hm_down<<<dn_grid, 256, SMEM_DYN>>>(hWd, hsWd);                    // 7

    combine_kernel<<<(T_TOK * H_DIM) / 256, 256>>>(out, sgate);        // 8
    aux_kernel<<<1, 256>>>(out);                                       // 9
}